// round 4
// baseline (speedup 1.0000x reference)
#include <cuda_runtime.h>
#include <cuda_bf16.h>
#include <math.h>

// Problem dims (fixed by setup_inputs)
#define BB 8
#define CC 256
#define HH 64
#define WW 64
#define NN 4096          // H*W
#define GROUPS 16

// ---------------- scratch (static device globals; no allocations) -------------
__device__ float g_yh[BB * CC * HH];          // row means  (b,c,h)
__device__ float g_yw[BB * CC * WW];          // col means  (b,c,w)
__device__ float g_xh[BB * CC * HH];          // gn+sigmoid of yh
__device__ float g_xw[BB * CC * WW];          // gn+sigmoid of yw
__device__ float g_qkv[(size_t)BB * 3 * CC * NN];      // 100.7 MB
__device__ float g_S[(size_t)BB * NN * NN];            // 536.9 MB scores / probs

// ---------------- kernel 1: row & column means -------------------------------
// block per (b,c), 64 threads
__global__ void mean_kernel(const float* __restrict__ x,
                            float* __restrict__ yh, float* __restrict__ yw) {
    __shared__ float tile[64][65];
    const int bc = blockIdx.x;                 // 0 .. B*C-1
    const float* xp = x + (size_t)bc * (HH * WW);
    const int t = threadIdx.x;                 // 0..63 (column w)
    float accw = 0.0f;
    #pragma unroll 8
    for (int h = 0; h < HH; ++h) {
        float v = xp[h * WW + t];
        tile[h][t] = v;
        accw += v;
    }
    yw[(size_t)bc * WW + t] = accw * (1.0f / WW);
    __syncthreads();
    float acch = 0.0f;
    #pragma unroll 8
    for (int w = 0; w < WW; ++w) acch += tile[t][w];
    yh[(size_t)bc * HH + t] = acch * (1.0f / HH);
}

// ---------------- kernel 2: z = W1 @ y + b1, GroupNorm, sigmoid -------------
// grid = B*2 (branch 0 = h, 1 = w), 256 threads, thread d owns channel d (64 l's)
__global__ void gn_kernel(const float* __restrict__ w1, const float* __restrict__ b1,
                          const float* __restrict__ gamma, const float* __restrict__ beta) {
    const int b  = blockIdx.x >> 1;
    const int br = blockIdx.x & 1;
    const float* y   = (br ? g_yw : g_yh) + (size_t)b * CC * 64;
    float*       out = (br ? g_xw : g_xh) + (size_t)b * CC * 64;
    const int d = threadIdx.x;                 // channel
    __shared__ float ys[64][65];

    float acc[64];
    const float bias = b1[d];
    #pragma unroll
    for (int l = 0; l < 64; ++l) acc[l] = bias;

    for (int kc = 0; kc < 4; ++kc) {
        __syncthreads();
        #pragma unroll
        for (int i = 0; i < 16; ++i) {
            int idx = d + i * 256;             // 4096 elems
            int k = idx >> 6, l = idx & 63;
            ys[k][l] = y[(size_t)(kc * 64 + k) * 64 + l];
        }
        __syncthreads();
        #pragma unroll 4
        for (int k = 0; k < 64; ++k) {
            float wv = w1[(size_t)d * CC + kc * 64 + k];
            #pragma unroll
            for (int l = 0; l < 64; ++l) acc[l] += wv * ys[k][l];
        }
    }

    // group norm over 16 channels x 64 l  (group = d>>4, 16 consecutive threads)
    float s = 0.0f, s2 = 0.0f;
    #pragma unroll
    for (int l = 0; l < 64; ++l) { s += acc[l]; s2 += acc[l] * acc[l]; }
    #pragma unroll
    for (int off = 8; off > 0; off >>= 1) {
        s  += __shfl_down_sync(0xffffffffu, s,  off, 16);
        s2 += __shfl_down_sync(0xffffffffu, s2, off, 16);
    }
    s  = __shfl_sync(0xffffffffu, s,  0, 16);
    s2 = __shfl_sync(0xffffffffu, s2, 0, 16);
    const float mu  = s * (1.0f / 1024.0f);
    const float var = s2 * (1.0f / 1024.0f) - mu * mu;
    const float rstd = rsqrtf(var + 1e-5f);
    const float ga = gamma[d], be = beta[d];
    #pragma unroll
    for (int l = 0; l < 64; ++l) {
        float zn = (acc[l] - mu) * rstd;
        float tt = zn * ga + be;
        out[(size_t)d * 64 + l] = 1.0f / (1.0f + expf(-tt));
    }
}

// ---------------- tiled fp32 GEMM: C(MxN) = A(MxK) * B(KxN) ------------------
// TA: A stored (K,M) row-major;  TB: B stored (N,K) row-major.
template<bool TA, bool TB>
__global__ __launch_bounds__(256)
void gemm128(const float* __restrict__ A, const float* __restrict__ B,
             float* __restrict__ C,
             int M, int N, int K, int lda, int ldb, int ldc,
             size_t sA, size_t sB, size_t sC) {
    A += (size_t)blockIdx.z * sA;
    B += (size_t)blockIdx.z * sB;
    C += (size_t)blockIdx.z * sC;
    const int m0 = blockIdx.y * 128;
    const int n0 = blockIdx.x * 128;
    __shared__ float As[16][132];
    __shared__ float Bs[16][132];
    const int tid = threadIdx.x;
    const int tx = tid & 15, ty = tid >> 4;

    float acc[8][8];
    #pragma unroll
    for (int i = 0; i < 8; ++i)
        #pragma unroll
        for (int j = 0; j < 8; ++j) acc[i][j] = 0.0f;

    for (int kt = 0; kt < K; kt += 16) {
        #pragma unroll
        for (int i = 0; i < 8; ++i) {
            int idx = tid + i * 256;
            if (TA) { int k = idx >> 7, m = idx & 127; As[k][m] = A[(size_t)(kt + k) * lda + m0 + m]; }
            else    { int m = idx >> 4, k = idx & 15;  As[k][m] = A[(size_t)(m0 + m) * lda + kt + k]; }
        }
        #pragma unroll
        for (int i = 0; i < 8; ++i) {
            int idx = tid + i * 256;
            if (TB) { int n = idx >> 4, k = idx & 15;  Bs[k][n] = B[(size_t)(n0 + n) * ldb + kt + k]; }
            else    { int k = idx >> 7, n = idx & 127; Bs[k][n] = B[(size_t)(kt + k) * ldb + n0 + n]; }
        }
        __syncthreads();
        #pragma unroll
        for (int k = 0; k < 16; ++k) {
            float a[8], b[8];
            *(float4*)&a[0] = *(const float4*)&As[k][ty * 8];
            *(float4*)&a[4] = *(const float4*)&As[k][ty * 8 + 4];
            *(float4*)&b[0] = *(const float4*)&Bs[k][tx * 8];
            *(float4*)&b[4] = *(const float4*)&Bs[k][tx * 8 + 4];
            #pragma unroll
            for (int i = 0; i < 8; ++i)
                #pragma unroll
                for (int j = 0; j < 8; ++j) acc[i][j] += a[i] * b[j];
        }
        __syncthreads();
    }

    #pragma unroll
    for (int i = 0; i < 8; ++i) {
        size_t crow = (size_t)(m0 + ty * 8 + i) * ldc + n0;
        *(float4*)&C[crow + tx * 8]     = make_float4(acc[i][0], acc[i][1], acc[i][2], acc[i][3]);
        *(float4*)&C[crow + tx * 8 + 4] = make_float4(acc[i][4], acc[i][5], acc[i][6], acc[i][7]);
    }
}

// ---------------- softmax over rows of S (scale folded in) -------------------
// block per row (B*N rows), 256 threads, 16 elems each
__global__ void softmax_kernel(float* __restrict__ S, float scale) {
    float* r = S + (size_t)blockIdx.x * NN;
    const int t = threadIdx.x;
    float v[16];
    float m = -1e30f;
    #pragma unroll
    for (int i = 0; i < 16; ++i) { v[i] = r[i * 256 + t] * scale; m = fmaxf(m, v[i]); }

    __shared__ float red[8];
    const int lane = t & 31, wid = t >> 5;
    #pragma unroll
    for (int off = 16; off > 0; off >>= 1) m = fmaxf(m, __shfl_xor_sync(0xffffffffu, m, off));
    if (lane == 0) red[wid] = m;
    __syncthreads();
    m = red[0];
    #pragma unroll
    for (int w = 1; w < 8; ++w) m = fmaxf(m, red[w]);

    float s = 0.0f;
    #pragma unroll
    for (int i = 0; i < 16; ++i) { v[i] = expf(v[i] - m); s += v[i]; }
    #pragma unroll
    for (int off = 16; off > 0; off >>= 1) s += __shfl_xor_sync(0xffffffffu, s, off);
    __syncthreads();
    if (lane == 0) red[wid] = s;
    __syncthreads();
    s = 0.0f;
    #pragma unroll
    for (int w = 0; w < 8; ++w) s += red[w];
    const float inv = 1.0f / s;
    #pragma unroll
    for (int i = 0; i < 16; ++i) r[i * 256 + t] = v[i] * inv;
}

// ---------------- final ELA multiply-add epilogue ----------------------------
// out[b,c,h,w] += x * xh[b,c,h] * xw[b,c,w];  float4 over w
__global__ void ela_add_kernel(const float* __restrict__ x, float* __restrict__ out) {
    size_t i = (size_t)blockIdx.x * 256 + threadIdx.x;   // index of float4
    size_t i4 = i * 4;
    int w  = (int)(i4 & 63);
    int h  = (int)((i4 >> 6) & 63);
    size_t bc = i4 >> 12;
    float sh = g_xh[bc * 64 + h];
    const float* xwp = &g_xw[bc * 64 + w];
    float4 xv = ((const float4*)x)[i];
    float4 ov = ((float4*)out)[i];
    ov.x += xv.x * sh * xwp[0];
    ov.y += xv.y * sh * xwp[1];
    ov.z += xv.z * sh * xwp[2];
    ov.w += xv.w * sh * xwp[3];
    ((float4*)out)[i] = ov;
}

// ---------------- launch ------------------------------------------------------
extern "C" void kernel_launch(void* const* d_in, const int* in_sizes, int n_in,
                              void* d_out, int out_size) {
    const float* x      = (const float*)d_in[0];
    const float* w_qkv  = (const float*)d_in[1];
    const float* w1     = (const float*)d_in[2];
    const float* b1     = (const float*)d_in[3];
    const float* gamma  = (const float*)d_in[4];
    const float* beta   = (const float*)d_in[5];
    float* out = (float*)d_out;

    void *pqkv_v, *pS_v, *pyh_v, *pyw_v;
    cudaGetSymbolAddress(&pqkv_v, g_qkv);
    cudaGetSymbolAddress(&pS_v, g_S);
    cudaGetSymbolAddress(&pyh_v, g_yh);
    cudaGetSymbolAddress(&pyw_v, g_yw);
    float* pqkv = (float*)pqkv_v;
    float* pS   = (float*)pS_v;

    // 1) means
    mean_kernel<<<BB * CC, 64>>>(x, (float*)pyh_v, (float*)pyw_v);

    // 2) fused GEMM + GroupNorm + sigmoid for both branches
    gn_kernel<<<BB * 2, 256>>>(w1, b1, gamma, beta);

    // 3) qkv = w_qkv (768x256) @ x_b (256x4096)
    {
        dim3 g(NN / 128, (3 * CC) / 128, BB);
        gemm128<false, false><<<g, 256>>>(w_qkv, x, pqkv,
                                          3 * CC, NN, CC,
                                          CC, NN, NN,
                                          (size_t)0, (size_t)CC * NN, (size_t)3 * CC * NN);
    }

    // 4) S = q^T k   (M=N=4096, K=256), A transposed view of q
    {
        dim3 g(NN / 128, NN / 128, BB);
        gemm128<true, false><<<g, 256>>>(pqkv,                     // q at channel 0
                                         pqkv + (size_t)CC * NN,   // k
                                         pS,
                                         NN, NN, CC,
                                         NN, NN, NN,
                                         (size_t)3 * CC * NN, (size_t)3 * CC * NN,
                                         (size_t)NN * NN);
    }

    // 5) softmax rows with scale = c^-0.5 = 1/16
    softmax_kernel<<<BB * NN, 256>>>(pS, 0.0625f);

    // 6) O = v (256x4096) @ P^T  -> d_out  (M=256, N=4096, K=4096)
    {
        dim3 g(NN / 128, CC / 128, BB);
        gemm128<false, true><<<g, 256>>>(pqkv + (size_t)2 * CC * NN, // v
                                         pS, out,
                                         CC, NN, NN,
                                         NN, NN, NN,
                                         (size_t)3 * CC * NN, (size_t)NN * NN,
                                         (size_t)CC * NN);
    }

    // 7) out += x * xh * xw
    ela_add_kernel<<<(BB * CC * HH * WW / 4) / 256, 256>>>(x, out);
}

// round 8
// speedup vs baseline: 2.9406x; 2.9406x over previous
#include <cuda_runtime.h>
#include <cuda_bf16.h>
#include <math.h>
#include <stdint.h>

#define BB 8
#define CC 256
#define HH 64
#define WW 64
#define NN 4096
#define GROUPS 16

#define SWZ(off) ((off) ^ (((off) >> 3) & 0x70))

__device__ __forceinline__ uint32_t smem_to_u32(const void* p) {
    uint32_t a;
    asm("{ .reg .u64 t; cvta.to.shared.u64 t, %1; cvt.u32.u64 %0, t; }" : "=r"(a) : "l"(p));
    return a;
}

#define LDSM_X4(r0, r1, r2, r3, addr) \
    asm volatile("ldmatrix.sync.aligned.m8n8.x4.shared.b16 {%0,%1,%2,%3}, [%4];" \
                 : "=r"(r0), "=r"(r1), "=r"(r2), "=r"(r3) : "r"(addr))

#define MMA_BF16(d, a, b) \
    asm volatile("mma.sync.aligned.m16n8k16.row.col.f32.bf16.bf16.f32 " \
                 "{%0,%1,%2,%3}, {%4,%5,%6,%7}, {%8,%9}, {%0,%1,%2,%3};" \
                 : "+f"((d)[0]), "+f"((d)[1]), "+f"((d)[2]), "+f"((d)[3]) \
                 : "r"((a)[0]), "r"((a)[1]), "r"((a)[2]), "r"((a)[3]), \
                   "r"((b)[0]), "r"((b)[1]))

#define CP_ASYNC16(dst, src) \
    asm volatile("cp.async.cg.shared.global [%0], [%1], 16;" :: "r"(dst), "l"(src))

// ---------------- scratch ----------------------------------------------------
__device__ float g_yh[BB * CC * HH];
__device__ float g_yw[BB * CC * WW];
__device__ float g_xh[BB * CC * HH];
__device__ float g_xw[BB * CC * WW];
__device__ __align__(256) float g_qkv[(size_t)BB * 3 * CC * NN];
__device__ __align__(256) float g_S[(size_t)BB * NN * NN];
__device__ __align__(256) __nv_bfloat16 g_whl[768 * 512];                 // W_qkv hi|lo
__device__ __align__(256) __nv_bfloat16 g_xT [(size_t)BB * NN * 512];     // x^T hi|lo
__device__ __align__(256) __nv_bfloat16 g_qT [(size_t)BB * NN * 512];     // [n][hi256|lo256]
__device__ __align__(256) __nv_bfloat16 g_kT [(size_t)BB * NN * 512];
__device__ __align__(256) __nv_bfloat16 g_v  [(size_t)BB * CC * 8192];    // [c][hi4096|lo4096]
__device__ __align__(256) __nv_bfloat16 g_P  [(size_t)BB * NN * 8192];    // [n][hi4096|lo4096]

// ---------------- kernel 1: row & column means -------------------------------
__global__ void mean_kernel(const float* __restrict__ x,
                            float* __restrict__ yh, float* __restrict__ yw) {
    __shared__ float tile[64][65];
    const int bc = blockIdx.x;
    const float* xp = x + (size_t)bc * (HH * WW);
    const int t = threadIdx.x;
    float accw = 0.0f;
    #pragma unroll 8
    for (int h = 0; h < HH; ++h) { float v = xp[h * WW + t]; tile[h][t] = v; accw += v; }
    yw[(size_t)bc * WW + t] = accw * (1.0f / WW);
    __syncthreads();
    float acch = 0.0f;
    #pragma unroll 8
    for (int w = 0; w < WW; ++w) acch += tile[t][w];
    yh[(size_t)bc * HH + t] = acch * (1.0f / HH);
}

// ---------------- kernel 2: GN branch ----------------------------------------
__global__ void gn_kernel(const float* __restrict__ w1, const float* __restrict__ b1,
                          const float* __restrict__ gamma, const float* __restrict__ beta) {
    const int b  = blockIdx.x >> 1;
    const int br = blockIdx.x & 1;
    const float* y   = (br ? g_yw : g_yh) + (size_t)b * CC * 64;
    float*       out = (br ? g_xw : g_xh) + (size_t)b * CC * 64;
    const int d = threadIdx.x;
    __shared__ float ys[64][65];
    float acc[64];
    const float bias = b1[d];
    #pragma unroll
    for (int l = 0; l < 64; ++l) acc[l] = bias;
    for (int kc = 0; kc < 4; ++kc) {
        __syncthreads();
        #pragma unroll
        for (int i = 0; i < 16; ++i) {
            int idx = d + i * 256;
            int k = idx >> 6, l = idx & 63;
            ys[k][l] = y[(size_t)(kc * 64 + k) * 64 + l];
        }
        __syncthreads();
        #pragma unroll 4
        for (int k = 0; k < 64; ++k) {
            float wv = w1[(size_t)d * CC + kc * 64 + k];
            #pragma unroll
            for (int l = 0; l < 64; ++l) acc[l] += wv * ys[k][l];
        }
    }
    float s = 0.0f, s2 = 0.0f;
    #pragma unroll
    for (int l = 0; l < 64; ++l) { s += acc[l]; s2 += acc[l] * acc[l]; }
    #pragma unroll
    for (int off = 8; off > 0; off >>= 1) {
        s  += __shfl_down_sync(0xffffffffu, s,  off, 16);
        s2 += __shfl_down_sync(0xffffffffu, s2, off, 16);
    }
    s  = __shfl_sync(0xffffffffu, s,  0, 16);
    s2 = __shfl_sync(0xffffffffu, s2, 0, 16);
    const float mu  = s * (1.0f / 1024.0f);
    const float var = s2 * (1.0f / 1024.0f) - mu * mu;
    const float rstd = rsqrtf(var + 1e-5f);
    const float ga = gamma[d], be = beta[d];
    #pragma unroll
    for (int l = 0; l < 64; ++l) {
        float zn = (acc[l] - mu) * rstd;
        float tt = zn * ga + be;
        out[(size_t)d * 64 + l] = 1.0f / (1.0f + expf(-tt));
    }
}

// ---------------- hi/lo split of W_qkv ---------------------------------------
__global__ void split_w_kernel(const float* __restrict__ w) {
    int i = blockIdx.x * 256 + threadIdx.x;        // 768*256
    int d = i >> 8, c = i & 255;
    float v = w[i];
    __nv_bfloat16 hi = __float2bfloat16(v);
    __nv_bfloat16 lo = __float2bfloat16(v - __bfloat162float(hi));
    g_whl[d * 512 + c]       = hi;
    g_whl[d * 512 + 256 + c] = lo;
}

// ---------------- transpose + hi/lo split of x -------------------------------
// x [b][256][4096] -> xT [b][4096][hi256|lo256]
__global__ void splitT_x_kernel(const float* __restrict__ x) {
    __shared__ float tile[32][33];
    const int c0 = blockIdx.x * 32, n0 = blockIdx.y * 32, b = blockIdx.z;
    const int tx = threadIdx.x, ty = threadIdx.y;
    const float* src = x + ((size_t)b * CC + c0) * NN + n0;
    #pragma unroll
    for (int i = 0; i < 4; ++i) tile[ty + 8 * i][tx] = src[(size_t)(ty + 8 * i) * NN + tx];
    __syncthreads();
    #pragma unroll
    for (int i = 0; i < 4; ++i) {
        int n = n0 + ty + 8 * i;
        float v = tile[tx][ty + 8 * i];
        __nv_bfloat16 hi = __float2bfloat16(v);
        __nv_bfloat16 lo = __float2bfloat16(v - __bfloat162float(hi));
        size_t base = ((size_t)b * NN + n) * 512;
        g_xT[base + c0 + tx]       = hi;
        g_xT[base + 256 + c0 + tx] = lo;
    }
}

// ---------------- qkv fp32 -> bf16 hi/lo (q,k transposed; v K-major) ---------
__global__ void convert_kernel(const float* __restrict__ qkv) {
    __shared__ float tile[32][33];
    const int d0 = blockIdx.x * 32, n0 = blockIdx.y * 32, b = blockIdx.z;
    const int tx = threadIdx.x, ty = threadIdx.y;
    const float* src = qkv + ((size_t)b * 768 + d0) * NN + n0;
    #pragma unroll
    for (int i = 0; i < 4; ++i) tile[ty + 8 * i][tx] = src[(size_t)(ty + 8 * i) * NN + tx];
    __syncthreads();
    if (d0 < 512) {
        __nv_bfloat16* dst = (d0 < 256) ? g_qT : g_kT;
        const int dd0 = d0 & 255;
        #pragma unroll
        for (int i = 0; i < 4; ++i) {
            int n = n0 + ty + 8 * i;
            float val = tile[tx][ty + 8 * i];
            __nv_bfloat16 hi = __float2bfloat16(val);
            __nv_bfloat16 lo = __float2bfloat16(val - __bfloat162float(hi));
            size_t base = ((size_t)b * NN + n) * 512;
            dst[base + dd0 + tx]       = hi;
            dst[base + 256 + dd0 + tx] = lo;
        }
    } else {
        #pragma unroll
        for (int i = 0; i < 4; ++i) {
            int c = d0 - 512 + ty + 8 * i;
            float val = tile[ty + 8 * i][tx];
            __nv_bfloat16 hi = __float2bfloat16(val);
            __nv_bfloat16 lo = __float2bfloat16(val - __bfloat162float(hi));
            size_t base = ((size_t)b * CC + c) * 8192;
            g_v[base + n0 + tx]        = hi;
            g_v[base + 4096 + n0 + tx] = lo;
        }
    }
}

// ---------------- bf16 mma.sync GEMM: C[m][n] = Σ_k A[m][k] B[n][k] ----------
// A stored [M][2K] (hi|lo), B stored [N][2K] (hi|lo). 3-term split along K':
//   term 0: Ahi·Bhi, term 1: Ahi·Blo, term 2: Alo·Bhi.  nchunks = 3*K/64.
__global__ __launch_bounds__(256)
void hmma_kernel(const __nv_bfloat16* __restrict__ A, const __nv_bfloat16* __restrict__ B,
                 float* __restrict__ C, int lda, int ldb, int ldc, int K,
                 size_t sA, size_t sB, size_t sC) {
    extern __shared__ char smem[];
    const uint32_t sb = smem_to_u32(smem);
    const int tid = threadIdx.x, lane = tid & 31, wid = tid >> 5;
    const int wm = wid & 3, wn = wid >> 2;
    A += (size_t)blockIdx.z * sA;
    B += (size_t)blockIdx.z * sB;
    C += (size_t)blockIdx.z * sC;
    const int m0 = blockIdx.y * 128, n0 = blockIdx.x * 128;
    const uint32_t offA[2] = {0u, 32768u};
    const uint32_t offB[2] = {16384u, 49152u};
    const int cpt = K >> 6;
    const int nch = 3 * cpt;

    float acc[2][8][4];
    #pragma unroll
    for (int mi = 0; mi < 2; ++mi)
        #pragma unroll
        for (int ni = 0; ni < 8; ++ni)
            #pragma unroll
            for (int q = 0; q < 4; ++q) acc[mi][ni][q] = 0.0f;

#define LOADC(j, buf) do {                                                               \
    int t_ = (j) / cpt, i_ = (j) % cpt;                                                  \
    int kA = ((t_ == 2) ? K : 0) + i_ * 64;                                              \
    int kB = ((t_ == 1) ? K : 0) + i_ * 64;                                              \
    _Pragma("unroll")                                                                    \
    for (int it = 0; it < 4; ++it) {                                                     \
        int id = tid + it * 256; int r = id >> 3, c8 = id & 7;                           \
        CP_ASYNC16(sb + offA[buf] + SWZ((uint32_t)(r * 128 + c8 * 16)),                  \
                   A + (size_t)(m0 + r) * lda + kA + c8 * 8);                            \
        CP_ASYNC16(sb + offB[buf] + SWZ((uint32_t)(r * 128 + c8 * 16)),                  \
                   B + (size_t)(n0 + r) * ldb + kB + c8 * 8);                            \
    }                                                                                    \
    asm volatile("cp.async.commit_group;");                                              \
} while (0)

    LOADC(0, 0);
    for (int j = 0; j < nch; ++j) {
        const int buf = j & 1;
        if (j + 1 < nch) {
            LOADC(j + 1, buf ^ 1);
            asm volatile("cp.async.wait_group 1;");
        } else {
            asm volatile("cp.async.wait_group 0;");
        }
        __syncthreads();
        const uint32_t a_base = sb + offA[buf];
        const uint32_t b_base = sb + offB[buf];
        #pragma unroll
        for (int ks = 0; ks < 4; ++ks) {
            const int k0 = ks * 16;
            uint32_t af[2][4];
            #pragma unroll
            for (int mi = 0; mi < 2; ++mi) {
                uint32_t off = (uint32_t)((wm * 32 + mi * 16 + (lane & 15)) * 128 +
                                          (k0 + ((lane >> 4) << 3)) * 2);
                LDSM_X4(af[mi][0], af[mi][1], af[mi][2], af[mi][3], a_base + SWZ(off));
            }
            uint32_t bf_[4][4];
            #pragma unroll
            for (int nj = 0; nj < 4; ++nj) {
                uint32_t off = (uint32_t)((wn * 64 + nj * 16 + (lane & 7) + ((lane >> 4) << 3)) * 128 +
                                          (k0 + (((lane >> 3) & 1) << 3)) * 2);
                LDSM_X4(bf_[nj][0], bf_[nj][1], bf_[nj][2], bf_[nj][3], b_base + SWZ(off));
            }
            #pragma unroll
            for (int mi = 0; mi < 2; ++mi)
                #pragma unroll
                for (int nj = 0; nj < 4; ++nj) {
                    MMA_BF16(acc[mi][nj * 2],     af[mi], &bf_[nj][0]);
                    MMA_BF16(acc[mi][nj * 2 + 1], af[mi], &bf_[nj][2]);
                }
        }
        __syncthreads();
    }
#undef LOADC

    const int group = lane >> 2, tig = lane & 3;
    #pragma unroll
    for (int mi = 0; mi < 2; ++mi)
        #pragma unroll
        for (int ni = 0; ni < 8; ++ni) {
            int row = m0 + wm * 32 + mi * 16 + group;
            int col = n0 + wn * 64 + ni * 8 + tig * 2;
            *(float2*)&C[(size_t)row * ldc + col]       = make_float2(acc[mi][ni][0], acc[mi][ni][1]);
            *(float2*)&C[(size_t)(row + 8) * ldc + col] = make_float2(acc[mi][ni][2], acc[mi][ni][3]);
        }
}

// ---------------- softmax: fp32 S row -> bf16 hi/lo P row --------------------
__global__ void softmax_kernel(const float* __restrict__ S, __nv_bfloat16* __restrict__ P,
                               float scale) {
    const float* r = S + (size_t)blockIdx.x * NN;
    __nv_bfloat16* prow = P + (size_t)blockIdx.x * 8192;
    const int t = threadIdx.x;
    float v[16];
    float m = -1e30f;
    #pragma unroll
    for (int i = 0; i < 16; ++i) { v[i] = r[i * 256 + t] * scale; m = fmaxf(m, v[i]); }
    __shared__ float red[8];
    const int lane = t & 31, wd = t >> 5;
    #pragma unroll
    for (int off = 16; off > 0; off >>= 1) m = fmaxf(m, __shfl_xor_sync(0xffffffffu, m, off));
    if (lane == 0) red[wd] = m;
    __syncthreads();
    m = red[0];
    #pragma unroll
    for (int w = 1; w < 8; ++w) m = fmaxf(m, red[w]);
    float s = 0.0f;
    #pragma unroll
    for (int i = 0; i < 16; ++i) { v[i] = expf(v[i] - m); s += v[i]; }
    #pragma unroll
    for (int off = 16; off > 0; off >>= 1) s += __shfl_xor_sync(0xffffffffu, s, off);
    __syncthreads();
    if (lane == 0) red[wd] = s;
    __syncthreads();
    s = 0.0f;
    #pragma unroll
    for (int w = 0; w < 8; ++w) s += red[w];
    const float inv = 1.0f / s;
    #pragma unroll
    for (int i = 0; i < 16; ++i) {
        float p = v[i] * inv;
        __nv_bfloat16 hi = __float2bfloat16(p);
        __nv_bfloat16 lo = __float2bfloat16(p - __bfloat162float(hi));
        prow[i * 256 + t]        = hi;
        prow[4096 + i * 256 + t] = lo;
    }
}

// ---------------- final ELA multiply-add -------------------------------------
__global__ void ela_add_kernel(const float* __restrict__ x, float* __restrict__ out) {
    size_t i = (size_t)blockIdx.x * 256 + threadIdx.x;
    size_t i4 = i * 4;
    int w  = (int)(i4 & 63);
    int h  = (int)((i4 >> 6) & 63);
    size_t bc = i4 >> 12;
    float sh = g_xh[bc * 64 + h];
    const float* xwp = &g_xw[bc * 64 + w];
    float4 xv = ((const float4*)x)[i];
    float4 ov = ((float4*)out)[i];
    ov.x += xv.x * sh * xwp[0];
    ov.y += xv.y * sh * xwp[1];
    ov.z += xv.z * sh * xwp[2];
    ov.w += xv.w * sh * xwp[3];
    ((float4*)out)[i] = ov;
}

// ---------------- launch ------------------------------------------------------
extern "C" void kernel_launch(void* const* d_in, const int* in_sizes, int n_in,
                              void* d_out, int out_size) {
    const float* x      = (const float*)d_in[0];
    const float* w_qkv  = (const float*)d_in[1];
    const float* w1     = (const float*)d_in[2];
    const float* b1     = (const float*)d_in[3];
    const float* gamma  = (const float*)d_in[4];
    const float* beta   = (const float*)d_in[5];
    float* out = (float*)d_out;

    void *pqkv_v, *pS_v, *pyh_v, *pyw_v, *pqT_v, *pkT_v, *pv_v, *pP_v, *pwhl_v, *pxT_v;
    cudaGetSymbolAddress(&pqkv_v, g_qkv);
    cudaGetSymbolAddress(&pS_v,   g_S);
    cudaGetSymbolAddress(&pyh_v,  g_yh);
    cudaGetSymbolAddress(&pyw_v,  g_yw);
    cudaGetSymbolAddress(&pqT_v,  g_qT);
    cudaGetSymbolAddress(&pkT_v,  g_kT);
    cudaGetSymbolAddress(&pv_v,   g_v);
    cudaGetSymbolAddress(&pP_v,   g_P);
    cudaGetSymbolAddress(&pwhl_v, g_whl);
    cudaGetSymbolAddress(&pxT_v,  g_xT);
    float* pqkv = (float*)pqkv_v;
    float* pS   = (float*)pS_v;

    static const int HSMEM = 65536;
    cudaFuncSetAttribute(hmma_kernel, cudaFuncAttributeMaxDynamicSharedMemorySize, HSMEM);

    // 1) means + GN branches
    mean_kernel<<<BB * CC, 64>>>(x, (float*)pyh_v, (float*)pyw_v);
    gn_kernel<<<BB * 2, 256>>>(w1, b1, gamma, beta);

    // 2) operand prep for qkv GEMM
    split_w_kernel<<<768, 256>>>(w_qkv);
    splitT_x_kernel<<<dim3(CC / 32, NN / 32, BB), dim3(32, 8)>>>(x);

    // 3) qkv = W_qkv @ x  (M=768, N=4096, K=256)
    hmma_kernel<<<dim3(NN / 128, 768 / 128, BB), 256, HSMEM>>>(
        (const __nv_bfloat16*)pwhl_v, (const __nv_bfloat16*)pxT_v, pqkv,
        512, 512, NN, 256, (size_t)0, (size_t)NN * 512, (size_t)768 * NN);

    // 4) split/transpose qkv to bf16 hi|lo buffers
    convert_kernel<<<dim3(768 / 32, NN / 32, BB), dim3(32, 8)>>>(pqkv);

    // 5) S = q^T k  (M=N=4096, K=256)
    hmma_kernel<<<dim3(NN / 128, NN / 128, BB), 256, HSMEM>>>(
        (const __nv_bfloat16*)pqT_v, (const __nv_bfloat16*)pkT_v, pS,
        512, 512, NN, 256, (size_t)NN * 512, (size_t)NN * 512, (size_t)NN * NN);

    // 6) softmax rows (scale 1/16) -> bf16 hi|lo P
    softmax_kernel<<<BB * NN, 256>>>(pS, (__nv_bfloat16*)pP_v, 0.0625f);

    // 7) O = V · P^T  (M=256, N=4096, K=4096)
    hmma_kernel<<<dim3(NN / 128, CC / 128, BB), 256, HSMEM>>>(
        (const __nv_bfloat16*)pv_v, (const __nv_bfloat16*)pP_v, out,
        8192, 8192, NN, 4096, (size_t)CC * 8192, (size_t)NN * 8192, (size_t)CC * NN);

    // 8) out += x * xh * xw
    ela_add_kernel<<<(BB * CC * HH * WW / 4) / 256, 256>>>(x, out);
}

// round 9
// speedup vs baseline: 3.9133x; 1.3308x over previous
#include <cuda_runtime.h>
#include <cuda_fp16.h>
#include <math.h>
#include <stdint.h>

#define BB 8
#define CC 256
#define HH 64
#define WW 64
#define NN 4096
#define GROUPS 16

#define SWZ(off) ((off) ^ (((off) >> 3) & 0x70))

__device__ __forceinline__ uint32_t smem_to_u32(const void* p) {
    uint32_t a;
    asm("{ .reg .u64 t; cvta.to.shared.u64 t, %1; cvt.u32.u64 %0, t; }" : "=r"(a) : "l"(p));
    return a;
}

#define LDSM_X4(r0, r1, r2, r3, addr) \
    asm volatile("ldmatrix.sync.aligned.m8n8.x4.shared.b16 {%0,%1,%2,%3}, [%4];" \
                 : "=r"(r0), "=r"(r1), "=r"(r2), "=r"(r3) : "r"(addr))

#define MMA_F16(d, a, b) \
    asm volatile("mma.sync.aligned.m16n8k16.row.col.f32.f16.f16.f32 " \
                 "{%0,%1,%2,%3}, {%4,%5,%6,%7}, {%8,%9}, {%0,%1,%2,%3};" \
                 : "+f"((d)[0]), "+f"((d)[1]), "+f"((d)[2]), "+f"((d)[3]) \
                 : "r"((a)[0]), "r"((a)[1]), "r"((a)[2]), "r"((a)[3]), \
                   "r"((b)[0]), "r"((b)[1]))

#define CP_ASYNC16(dst, src) \
    asm volatile("cp.async.cg.shared.global [%0], [%1], 16;" :: "r"(dst), "l"(src))

// ---------------- scratch ----------------------------------------------------
__device__ float g_yh[BB * CC * HH];
__device__ float g_yw[BB * CC * WW];
__device__ float g_xh[BB * CC * HH];
__device__ float g_xw[BB * CC * WW];
__device__ __align__(256) float g_qk32[(size_t)BB * 512 * NN];           // fp32 q,k rows only
__device__ __align__(256) float g_S[(size_t)BB * NN * NN];               // fp32 scores
__device__ __align__(256) __half g_whl[768 * 512];                       // W_qkv [d][hi256|lo256]
__device__ __align__(256) __half g_xT [(size_t)BB * NN * 256];           // x^T hi only
__device__ __align__(256) __half g_qT [(size_t)BB * NN * 512];           // [n][hi256|lo256]
__device__ __align__(256) __half g_kT [(size_t)BB * NN * 256];           // [n][hi256]
__device__ __align__(256) __half g_v  [(size_t)BB * CC * 8192];          // [c][hi4096|lo4096]
__device__ __align__(256) __half g_P  [(size_t)BB * NN * 4096];          // [n][hi4096]

// ---------------- kernel 1: row & column means -------------------------------
__global__ void mean_kernel(const float* __restrict__ x,
                            float* __restrict__ yh, float* __restrict__ yw) {
    __shared__ float tile[64][65];
    const int bc = blockIdx.x;
    const float* xp = x + (size_t)bc * (HH * WW);
    const int t = threadIdx.x;
    float accw = 0.0f;
    #pragma unroll 8
    for (int h = 0; h < HH; ++h) { float v = xp[h * WW + t]; tile[h][t] = v; accw += v; }
    yw[(size_t)bc * WW + t] = accw * (1.0f / WW);
    __syncthreads();
    float acch = 0.0f;
    #pragma unroll 8
    for (int w = 0; w < WW; ++w) acch += tile[t][w];
    yh[(size_t)bc * HH + t] = acch * (1.0f / HH);
}

// ---------------- kernel 2: GN branch ----------------------------------------
__global__ void gn_kernel(const float* __restrict__ w1, const float* __restrict__ b1,
                          const float* __restrict__ gamma, const float* __restrict__ beta) {
    const int b  = blockIdx.x >> 1;
    const int br = blockIdx.x & 1;
    const float* y   = (br ? g_yw : g_yh) + (size_t)b * CC * 64;
    float*       out = (br ? g_xw : g_xh) + (size_t)b * CC * 64;
    const int d = threadIdx.x;
    __shared__ float ys[64][65];
    float acc[64];
    const float bias = b1[d];
    #pragma unroll
    for (int l = 0; l < 64; ++l) acc[l] = bias;
    for (int kc = 0; kc < 4; ++kc) {
        __syncthreads();
        #pragma unroll
        for (int i = 0; i < 16; ++i) {
            int idx = d + i * 256;
            int k = idx >> 6, l = idx & 63;
            ys[k][l] = y[(size_t)(kc * 64 + k) * 64 + l];
        }
        __syncthreads();
        #pragma unroll 4
        for (int k = 0; k < 64; ++k) {
            float wv = w1[(size_t)d * CC + kc * 64 + k];
            #pragma unroll
            for (int l = 0; l < 64; ++l) acc[l] += wv * ys[k][l];
        }
    }
    float s = 0.0f, s2 = 0.0f;
    #pragma unroll
    for (int l = 0; l < 64; ++l) { s += acc[l]; s2 += acc[l] * acc[l]; }
    #pragma unroll
    for (int off = 8; off > 0; off >>= 1) {
        s  += __shfl_down_sync(0xffffffffu, s,  off, 16);
        s2 += __shfl_down_sync(0xffffffffu, s2, off, 16);
    }
    s  = __shfl_sync(0xffffffffu, s,  0, 16);
    s2 = __shfl_sync(0xffffffffu, s2, 0, 16);
    const float mu  = s * (1.0f / 1024.0f);
    const float var = s2 * (1.0f / 1024.0f) - mu * mu;
    const float rstd = rsqrtf(var + 1e-5f);
    const float ga = gamma[d], be = beta[d];
    #pragma unroll
    for (int l = 0; l < 64; ++l) {
        float zn = (acc[l] - mu) * rstd;
        float tt = zn * ga + be;
        out[(size_t)d * 64 + l] = 1.0f / (1.0f + expf(-tt));
    }
}

// ---------------- hi/lo split of W_qkv ---------------------------------------
__global__ void split_w_kernel(const float* __restrict__ w) {
    int i = blockIdx.x * 256 + threadIdx.x;        // 768*256
    int d = i >> 8, c = i & 255;
    float v = w[i];
    __half hi = __float2half_rn(v);
    __half lo = __float2half_rn(v - __half2float(hi));
    g_whl[d * 512 + c]       = hi;
    g_whl[d * 512 + 256 + c] = lo;
}

// ---------------- transpose x -> fp16 hi only --------------------------------
// x [b][256][4096] -> xT [b][4096][256]
__global__ void splitT_x_kernel(const float* __restrict__ x) {
    __shared__ float tile[32][33];
    const int c0 = blockIdx.x * 32, n0 = blockIdx.y * 32, b = blockIdx.z;
    const int tx = threadIdx.x, ty = threadIdx.y;
    const float* src = x + ((size_t)b * CC + c0) * NN + n0;
    #pragma unroll
    for (int i = 0; i < 4; ++i) tile[ty + 8 * i][tx] = src[(size_t)(ty + 8 * i) * NN + tx];
    __syncthreads();
    #pragma unroll
    for (int i = 0; i < 4; ++i) {
        int n = n0 + ty + 8 * i;
        g_xT[((size_t)b * NN + n) * 256 + c0 + tx] = __float2half_rn(tile[tx][ty + 8 * i]);
    }
}

// ---------------- q,k fp32 -> fp16 (q: hi|lo transposed; k: hi transposed) ---
__global__ void convert_kernel(const float* __restrict__ qk) {
    __shared__ float tile[32][33];
    const int d0 = blockIdx.x * 32, n0 = blockIdx.y * 32, b = blockIdx.z;
    const int tx = threadIdx.x, ty = threadIdx.y;
    const float* src = qk + ((size_t)b * 512 + d0) * NN + n0;
    #pragma unroll
    for (int i = 0; i < 4; ++i) tile[ty + 8 * i][tx] = src[(size_t)(ty + 8 * i) * NN + tx];
    __syncthreads();
    if (d0 < 256) {
        #pragma unroll
        for (int i = 0; i < 4; ++i) {
            int n = n0 + ty + 8 * i;
            float val = tile[tx][ty + 8 * i];
            __half hi = __float2half_rn(val);
            __half lo = __float2half_rn(val - __half2float(hi));
            size_t base = ((size_t)b * NN + n) * 512;
            g_qT[base + d0 + tx]       = hi;
            g_qT[base + 256 + d0 + tx] = lo;
        }
    } else {
        const int dd0 = d0 - 256;
        #pragma unroll
        for (int i = 0; i < 4; ++i) {
            int n = n0 + ty + 8 * i;
            g_kT[((size_t)b * NN + n) * 256 + dd0 + tx] =
                __float2half_rn(tile[tx][ty + 8 * i]);
        }
    }
}

// ---------------- fp16 mma.sync GEMM: C[m][n] = Σ_k A[m][k] B[n][k] ----------
// A stored [M][2K] (hi|lo), B stored [N][K] (hi only). 2-term split:
//   term 0: Ahi·Bhi, term 1: Alo·Bhi.  nchunks = 2*K/64, B chunks repeat.
// vmode: if Vout != nullptr and m0 >= 512, write V hi/lo fp16 instead of fp32 C.
__global__ __launch_bounds__(256)
void hmma_kernel(const __half* __restrict__ A, const __half* __restrict__ B,
                 float* __restrict__ C, __half* __restrict__ Vout,
                 int lda, int ldb, int ldc, int K,
                 size_t sA, size_t sB, size_t sC) {
    extern __shared__ char smem[];
    const uint32_t sb = smem_to_u32(smem);
    const int tid = threadIdx.x, lane = tid & 31, wid = tid >> 5;
    const int wm = wid & 3, wn = wid >> 2;
    A += (size_t)blockIdx.z * sA;
    B += (size_t)blockIdx.z * sB;
    C += (size_t)blockIdx.z * sC;
    const int m0 = blockIdx.y * 128, n0 = blockIdx.x * 128;
    const uint32_t offA[2] = {0u, 32768u};
    const uint32_t offB[2] = {16384u, 49152u};
    const int cpt = K >> 6;
    const int nch = 2 * cpt;

    float acc[2][8][4];
    #pragma unroll
    for (int mi = 0; mi < 2; ++mi)
        #pragma unroll
        for (int ni = 0; ni < 8; ++ni)
            #pragma unroll
            for (int q = 0; q < 4; ++q) acc[mi][ni][q] = 0.0f;

#define LOADC(j, buf) do {                                                               \
    int t_ = (j) / cpt, i_ = (j) % cpt;                                                  \
    int kA = t_ * K + i_ * 64;                                                           \
    int kB = i_ * 64;                                                                    \
    _Pragma("unroll")                                                                    \
    for (int it = 0; it < 4; ++it) {                                                     \
        int id = tid + it * 256; int r = id >> 3, c8 = id & 7;                           \
        CP_ASYNC16(sb + offA[buf] + SWZ((uint32_t)(r * 128 + c8 * 16)),                  \
                   A + (size_t)(m0 + r) * lda + kA + c8 * 8);                            \
        CP_ASYNC16(sb + offB[buf] + SWZ((uint32_t)(r * 128 + c8 * 16)),                  \
                   B + (size_t)(n0 + r) * ldb + kB + c8 * 8);                            \
    }                                                                                    \
    asm volatile("cp.async.commit_group;");                                              \
} while (0)

    LOADC(0, 0);
    for (int j = 0; j < nch; ++j) {
        const int buf = j & 1;
        if (j + 1 < nch) {
            LOADC(j + 1, buf ^ 1);
            asm volatile("cp.async.wait_group 1;");
        } else {
            asm volatile("cp.async.wait_group 0;");
        }
        __syncthreads();
        const uint32_t a_base = sb + offA[buf];
        const uint32_t b_base = sb + offB[buf];
        #pragma unroll
        for (int ks = 0; ks < 4; ++ks) {
            const int k0 = ks * 16;
            uint32_t af[2][4];
            #pragma unroll
            for (int mi = 0; mi < 2; ++mi) {
                uint32_t off = (uint32_t)((wm * 32 + mi * 16 + (lane & 15)) * 128 +
                                          (k0 + ((lane >> 4) << 3)) * 2);
                LDSM_X4(af[mi][0], af[mi][1], af[mi][2], af[mi][3], a_base + SWZ(off));
            }
            uint32_t bf_[4][4];
            #pragma unroll
            for (int nj = 0; nj < 4; ++nj) {
                uint32_t off = (uint32_t)((wn * 64 + nj * 16 + (lane & 7) + ((lane >> 4) << 3)) * 128 +
                                          (k0 + (((lane >> 3) & 1) << 3)) * 2);
                LDSM_X4(bf_[nj][0], bf_[nj][1], bf_[nj][2], bf_[nj][3], b_base + SWZ(off));
            }
            #pragma unroll
            for (int mi = 0; mi < 2; ++mi)
                #pragma unroll
                for (int nj = 0; nj < 4; ++nj) {
                    MMA_F16(acc[mi][nj * 2],     af[mi], &bf_[nj][0]);
                    MMA_F16(acc[mi][nj * 2 + 1], af[mi], &bf_[nj][2]);
                }
        }
        __syncthreads();
    }
#undef LOADC

    const int group = lane >> 2, tig = lane & 3;
    if (Vout != nullptr && m0 >= 512) {
        // V rows: write fp16 hi|lo to Vout[(c)][hi4096|lo4096]
        __half* vb = Vout + (size_t)blockIdx.z * CC * 8192;
        #pragma unroll
        for (int mi = 0; mi < 2; ++mi)
            #pragma unroll
            for (int ni = 0; ni < 8; ++ni) {
                int row = m0 + wm * 32 + mi * 16 + group;
                int col = n0 + wn * 64 + ni * 8 + tig * 2;
                #pragma unroll
                for (int half_ : {0, 1}) {
                    int rr = row + half_ * 8;
                    float v0 = acc[mi][ni][half_ * 2], v1 = acc[mi][ni][half_ * 2 + 1];
                    __half h0 = __float2half_rn(v0), h1 = __float2half_rn(v1);
                    __half l0 = __float2half_rn(v0 - __half2float(h0));
                    __half l1 = __float2half_rn(v1 - __half2float(h1));
                    size_t base = (size_t)(rr - 512) * 8192;
                    __half2 hh; hh.x = h0; hh.y = h1;
                    __half2 ll; ll.x = l0; ll.y = l1;
                    *(__half2*)&vb[base + col]        = hh;
                    *(__half2*)&vb[base + 4096 + col] = ll;
                }
            }
    } else {
        #pragma unroll
        for (int mi = 0; mi < 2; ++mi)
            #pragma unroll
            for (int ni = 0; ni < 8; ++ni) {
                int row = m0 + wm * 32 + mi * 16 + group;
                int col = n0 + wn * 64 + ni * 8 + tig * 2;
                *(float2*)&C[(size_t)row * ldc + col]       = make_float2(acc[mi][ni][0], acc[mi][ni][1]);
                *(float2*)&C[(size_t)(row + 8) * ldc + col] = make_float2(acc[mi][ni][2], acc[mi][ni][3]);
            }
    }
}

// ---------------- softmax: fp32 S row -> fp16 P row (hi only) ----------------
__global__ void softmax_kernel(const float* __restrict__ S, __half* __restrict__ P,
                               float scale) {
    const float* r = S + (size_t)blockIdx.x * NN;
    __half* prow = P + (size_t)blockIdx.x * 4096;
    const int t = threadIdx.x;
    float v[16];
    float m = -1e30f;
    #pragma unroll
    for (int i = 0; i < 16; ++i) { v[i] = r[i * 256 + t] * scale; m = fmaxf(m, v[i]); }
    __shared__ float red[8];
    const int lane = t & 31, wd = t >> 5;
    #pragma unroll
    for (int off = 16; off > 0; off >>= 1) m = fmaxf(m, __shfl_xor_sync(0xffffffffu, m, off));
    if (lane == 0) red[wd] = m;
    __syncthreads();
    m = red[0];
    #pragma unroll
    for (int w = 1; w < 8; ++w) m = fmaxf(m, red[w]);
    float s = 0.0f;
    #pragma unroll
    for (int i = 0; i < 16; ++i) { v[i] = expf(v[i] - m); s += v[i]; }
    #pragma unroll
    for (int off = 16; off > 0; off >>= 1) s += __shfl_xor_sync(0xffffffffu, s, off);
    __syncthreads();
    if (lane == 0) red[wd] = s;
    __syncthreads();
    s = 0.0f;
    #pragma unroll
    for (int w = 0; w < 8; ++w) s += red[w];
    const float inv = 1.0f / s;
    #pragma unroll
    for (int i = 0; i < 16; ++i)
        prow[i * 256 + t] = __float2half_rn(v[i] * inv);
}

// ---------------- final ELA multiply-add -------------------------------------
__global__ void ela_add_kernel(const float* __restrict__ x, float* __restrict__ out) {
    size_t i = (size_t)blockIdx.x * 256 + threadIdx.x;
    size_t i4 = i * 4;
    int w  = (int)(i4 & 63);
    int h  = (int)((i4 >> 6) & 63);
    size_t bc = i4 >> 12;
    float sh = g_xh[bc * 64 + h];
    const float* xwp = &g_xw[bc * 64 + w];
    float4 xv = ((const float4*)x)[i];
    float4 ov = ((float4*)out)[i];
    ov.x += xv.x * sh * xwp[0];
    ov.y += xv.y * sh * xwp[1];
    ov.z += xv.z * sh * xwp[2];
    ov.w += xv.w * sh * xwp[3];
    ((float4*)out)[i] = ov;
}

// ---------------- launch ------------------------------------------------------
extern "C" void kernel_launch(void* const* d_in, const int* in_sizes, int n_in,
                              void* d_out, int out_size) {
    const float* x      = (const float*)d_in[0];
    const float* w_qkv  = (const float*)d_in[1];
    const float* w1     = (const float*)d_in[2];
    const float* b1     = (const float*)d_in[3];
    const float* gamma  = (const float*)d_in[4];
    const float* beta   = (const float*)d_in[5];
    float* out = (float*)d_out;

    void *pqk32_v, *pS_v, *pyh_v, *pyw_v, *pqT_v, *pkT_v, *pv_v, *pP_v, *pwhl_v, *pxT_v;
    cudaGetSymbolAddress(&pqk32_v, g_qk32);
    cudaGetSymbolAddress(&pS_v,    g_S);
    cudaGetSymbolAddress(&pyh_v,   g_yh);
    cudaGetSymbolAddress(&pyw_v,   g_yw);
    cudaGetSymbolAddress(&pqT_v,   g_qT);
    cudaGetSymbolAddress(&pkT_v,   g_kT);
    cudaGetSymbolAddress(&pv_v,    g_v);
    cudaGetSymbolAddress(&pP_v,    g_P);
    cudaGetSymbolAddress(&pwhl_v,  g_whl);
    cudaGetSymbolAddress(&pxT_v,   g_xT);
    float* pqk32 = (float*)pqk32_v;
    float* pS    = (float*)pS_v;

    static const int HSMEM = 65536;
    cudaFuncSetAttribute(hmma_kernel, cudaFuncAttributeMaxDynamicSharedMemorySize, HSMEM);

    // 1) means + GN branches
    mean_kernel<<<BB * CC, 64>>>(x, (float*)pyh_v, (float*)pyw_v);
    gn_kernel<<<BB * 2, 256>>>(w1, b1, gamma, beta);

    // 2) operand prep for qkv GEMM
    split_w_kernel<<<768, 256>>>(w_qkv);
    splitT_x_kernel<<<dim3(CC / 32, NN / 32, BB), dim3(32, 8)>>>(x);

    // 3) qkv = W_qkv @ x  (M=768, N=4096, K=256); V rows written fp16 hi/lo
    hmma_kernel<<<dim3(NN / 128, 768 / 128, BB), 256, HSMEM>>>(
        (const __half*)pwhl_v, (const __half*)pxT_v, pqk32, (__half*)pv_v,
        512, 256, NN, 256, (size_t)0, (size_t)NN * 256, (size_t)512 * NN);

    // 4) split/transpose q,k to fp16 buffers
    convert_kernel<<<dim3(512 / 32, NN / 32, BB), dim3(32, 8)>>>(pqk32);

    // 5) S = q^T k  (M=N=4096, K=256)
    hmma_kernel<<<dim3(NN / 128, NN / 128, BB), 256, HSMEM>>>(
        (const __half*)pqT_v, (const __half*)pkT_v, pS, nullptr,
        512, 256, NN, 256, (size_t)NN * 512, (size_t)NN * 256, (size_t)NN * NN);

    // 6) softmax rows (scale 1/16) -> fp16 P
    softmax_kernel<<<BB * NN, 256>>>(pS, (__half*)pP_v, 0.0625f);

    // 7) O = V · P^T  (M=256, N=4096, K=4096)
    hmma_kernel<<<dim3(NN / 128, CC / 128, BB), 256, HSMEM>>>(
        (const __half*)pv_v, (const __half*)pP_v, out, nullptr,
        8192, 4096, NN, 4096, (size_t)CC * 8192, (size_t)NN * 4096, (size_t)CC * NN);

    // 8) out += x * xh * xw
    ela_add_kernel<<<(BB * CC * HH * WW / 4) / 256, 256>>>(x, out);
}

// round 10
// speedup vs baseline: 6.2344x; 1.5931x over previous
#include <cuda_runtime.h>
#include <cuda_fp16.h>
#include <math.h>
#include <stdint.h>

#define BB 8
#define CC 256
#define HH 64
#define WW 64
#define NN 4096
#define GROUPS 16

#define SWZ(off) ((off) ^ (((off) >> 3) & 0x70))

__device__ __forceinline__ uint32_t smem_to_u32(const void* p) {
    uint32_t a;
    asm("{ .reg .u64 t; cvta.to.shared.u64 t, %1; cvt.u32.u64 %0, t; }" : "=r"(a) : "l"(p));
    return a;
}

#define LDSM_X4(r0, r1, r2, r3, addr) \
    asm volatile("ldmatrix.sync.aligned.m8n8.x4.shared.b16 {%0,%1,%2,%3}, [%4];" \
                 : "=r"(r0), "=r"(r1), "=r"(r2), "=r"(r3) : "r"(addr))

#define MMA_F16(d, a, b) \
    asm volatile("mma.sync.aligned.m16n8k16.row.col.f32.f16.f16.f32 " \
                 "{%0,%1,%2,%3}, {%4,%5,%6,%7}, {%8,%9}, {%0,%1,%2,%3};" \
                 : "+f"((d)[0]), "+f"((d)[1]), "+f"((d)[2]), "+f"((d)[3]) \
                 : "r"((a)[0]), "r"((a)[1]), "r"((a)[2]), "r"((a)[3]), \
                   "r"((b)[0]), "r"((b)[1]))

#define CP_ASYNC16(dst, src) \
    asm volatile("cp.async.cg.shared.global [%0], [%1], 16;" :: "r"(dst), "l"(src))

// ---------------- scratch ----------------------------------------------------
__device__ float g_yh[BB * CC * HH];
__device__ float g_yw[BB * CC * WW];
__device__ float g_xh[BB * CC * HH];
__device__ float g_xw[BB * CC * WW];
__device__ __align__(256) float g_qk32[(size_t)BB * 512 * NN];           // fp32 q,k rows
__device__ __align__(256) float g_S[(size_t)BB * NN * NN];               // fp32 scores
__device__ __align__(256) __half g_wh [768 * 256];                       // W_qkv fp16
__device__ __align__(256) __half g_xT [(size_t)BB * NN * 256];           // x^T fp16
__device__ __align__(256) __half g_qT [(size_t)BB * NN * 256];           // q^T fp16
__device__ __align__(256) __half g_kT [(size_t)BB * NN * 256];           // k^T fp16
__device__ __align__(256) __half g_v  [(size_t)BB * CC * 4096];          // V fp16 (K-major)
__device__ __align__(256) __half g_P  [(size_t)BB * NN * 4096];          // P fp16

// ---------------- kernel 1: row & column means -------------------------------
__global__ void mean_kernel(const float* __restrict__ x,
                            float* __restrict__ yh, float* __restrict__ yw) {
    __shared__ float tile[64][65];
    const int bc = blockIdx.x;
    const float* xp = x + (size_t)bc * (HH * WW);
    const int t = threadIdx.x;
    float accw = 0.0f;
    #pragma unroll 8
    for (int h = 0; h < HH; ++h) { float v = xp[h * WW + t]; tile[h][t] = v; accw += v; }
    yw[(size_t)bc * WW + t] = accw * (1.0f / WW);
    __syncthreads();
    float acch = 0.0f;
    #pragma unroll 8
    for (int w = 0; w < WW; ++w) acch += tile[t][w];
    yh[(size_t)bc * HH + t] = acch * (1.0f / HH);
}

// ---------------- kernel 2: GN branch ----------------------------------------
__global__ void gn_kernel(const float* __restrict__ w1, const float* __restrict__ b1,
                          const float* __restrict__ gamma, const float* __restrict__ beta) {
    const int b  = blockIdx.x >> 1;
    const int br = blockIdx.x & 1;
    const float* y   = (br ? g_yw : g_yh) + (size_t)b * CC * 64;
    float*       out = (br ? g_xw : g_xh) + (size_t)b * CC * 64;
    const int d = threadIdx.x;
    __shared__ float ys[64][65];
    float acc[64];
    const float bias = b1[d];
    #pragma unroll
    for (int l = 0; l < 64; ++l) acc[l] = bias;
    for (int kc = 0; kc < 4; ++kc) {
        __syncthreads();
        #pragma unroll
        for (int i = 0; i < 16; ++i) {
            int idx = d + i * 256;
            int k = idx >> 6, l = idx & 63;
            ys[k][l] = y[(size_t)(kc * 64 + k) * 64 + l];
        }
        __syncthreads();
        #pragma unroll 4
        for (int k = 0; k < 64; ++k) {
            float wv = w1[(size_t)d * CC + kc * 64 + k];
            #pragma unroll
            for (int l = 0; l < 64; ++l) acc[l] += wv * ys[k][l];
        }
    }
    float s = 0.0f, s2 = 0.0f;
    #pragma unroll
    for (int l = 0; l < 64; ++l) { s += acc[l]; s2 += acc[l] * acc[l]; }
    #pragma unroll
    for (int off = 8; off > 0; off >>= 1) {
        s  += __shfl_down_sync(0xffffffffu, s,  off, 16);
        s2 += __shfl_down_sync(0xffffffffu, s2, off, 16);
    }
    s  = __shfl_sync(0xffffffffu, s,  0, 16);
    s2 = __shfl_sync(0xffffffffu, s2, 0, 16);
    const float mu  = s * (1.0f / 1024.0f);
    const float var = s2 * (1.0f / 1024.0f) - mu * mu;
    const float rstd = rsqrtf(var + 1e-5f);
    const float ga = gamma[d], be = beta[d];
    #pragma unroll
    for (int l = 0; l < 64; ++l) {
        float zn = (acc[l] - mu) * rstd;
        float tt = zn * ga + be;
        out[(size_t)d * 64 + l] = 1.0f / (1.0f + expf(-tt));
    }
}

// ---------------- W_qkv fp32 -> fp16 -----------------------------------------
__global__ void conv_w_kernel(const float* __restrict__ w) {
    int i = blockIdx.x * 256 + threadIdx.x;        // 768*256
    g_wh[i] = __float2half_rn(w[i]);
}

// ---------------- transpose x -> fp16 ----------------------------------------
__global__ void splitT_x_kernel(const float* __restrict__ x) {
    __shared__ float tile[32][33];
    const int c0 = blockIdx.x * 32, n0 = blockIdx.y * 32, b = blockIdx.z;
    const int tx = threadIdx.x, ty = threadIdx.y;
    const float* src = x + ((size_t)b * CC + c0) * NN + n0;
    #pragma unroll
    for (int i = 0; i < 4; ++i) tile[ty + 8 * i][tx] = src[(size_t)(ty + 8 * i) * NN + tx];
    __syncthreads();
    #pragma unroll
    for (int i = 0; i < 4; ++i) {
        int n = n0 + ty + 8 * i;
        g_xT[((size_t)b * NN + n) * 256 + c0 + tx] = __float2half_rn(tile[tx][ty + 8 * i]);
    }
}

// ---------------- q,k fp32 -> fp16 transposed --------------------------------
__global__ void convert_kernel(const float* __restrict__ qk) {
    __shared__ float tile[32][33];
    const int d0 = blockIdx.x * 32, n0 = blockIdx.y * 32, b = blockIdx.z;
    const int tx = threadIdx.x, ty = threadIdx.y;
    const float* src = qk + ((size_t)b * 512 + d0) * NN + n0;
    #pragma unroll
    for (int i = 0; i < 4; ++i) tile[ty + 8 * i][tx] = src[(size_t)(ty + 8 * i) * NN + tx];
    __syncthreads();
    __half* dst = (d0 < 256) ? g_qT : g_kT;
    const int dd0 = d0 & 255;
    #pragma unroll
    for (int i = 0; i < 4; ++i) {
        int n = n0 + ty + 8 * i;
        dst[((size_t)b * NN + n) * 256 + dd0 + tx] =
            __float2half_rn(tile[tx][ty + 8 * i]);
    }
}

// ---------------- fp16 mma.sync GEMM: C[m][n] = Σ_k A[m][k] B[n][k] ----------
// A [M][K] (lda), B [N][K] (ldb), K consumed in 64-wide chunks, double buffer.
// vmode: if Vout != nullptr and m0 >= 512, write fp16 V instead of fp32 C.
__global__ __launch_bounds__(256)
void hmma_kernel(const __half* __restrict__ A, const __half* __restrict__ B,
                 float* __restrict__ C, __half* __restrict__ Vout,
                 int lda, int ldb, int ldc, int K,
                 size_t sA, size_t sB, size_t sC) {
    extern __shared__ char smem[];
    const uint32_t sb = smem_to_u32(smem);
    const int tid = threadIdx.x, lane = tid & 31, wid = tid >> 5;
    const int wm = wid & 3, wn = wid >> 2;
    A += (size_t)blockIdx.z * sA;
    B += (size_t)blockIdx.z * sB;
    C += (size_t)blockIdx.z * sC;
    const int m0 = blockIdx.y * 128, n0 = blockIdx.x * 128;
    const uint32_t offA[2] = {0u, 32768u};
    const uint32_t offB[2] = {16384u, 49152u};
    const int nch = K >> 6;

    float acc[2][8][4];
    #pragma unroll
    for (int mi = 0; mi < 2; ++mi)
        #pragma unroll
        for (int ni = 0; ni < 8; ++ni)
            #pragma unroll
            for (int q = 0; q < 4; ++q) acc[mi][ni][q] = 0.0f;

#define LOADC(j, buf) do {                                                               \
    int k0_ = (j) * 64;                                                                  \
    _Pragma("unroll")                                                                    \
    for (int it = 0; it < 4; ++it) {                                                     \
        int id = tid + it * 256; int r = id >> 3, c8 = id & 7;                           \
        CP_ASYNC16(sb + offA[buf] + SWZ((uint32_t)(r * 128 + c8 * 16)),                  \
                   A + (size_t)(m0 + r) * lda + k0_ + c8 * 8);                           \
        CP_ASYNC16(sb + offB[buf] + SWZ((uint32_t)(r * 128 + c8 * 16)),                  \
                   B + (size_t)(n0 + r) * ldb + k0_ + c8 * 8);                           \
    }                                                                                    \
    asm volatile("cp.async.commit_group;");                                              \
} while (0)

    LOADC(0, 0);
    for (int j = 0; j < nch; ++j) {
        const int buf = j & 1;
        if (j + 1 < nch) {
            LOADC(j + 1, buf ^ 1);
            asm volatile("cp.async.wait_group 1;");
        } else {
            asm volatile("cp.async.wait_group 0;");
        }
        __syncthreads();
        const uint32_t a_base = sb + offA[buf];
        const uint32_t b_base = sb + offB[buf];
        #pragma unroll
        for (int ks = 0; ks < 4; ++ks) {
            const int k0 = ks * 16;
            uint32_t af[2][4];
            #pragma unroll
            for (int mi = 0; mi < 2; ++mi) {
                uint32_t off = (uint32_t)((wm * 32 + mi * 16 + (lane & 15)) * 128 +
                                          (k0 + ((lane >> 4) << 3)) * 2);
                LDSM_X4(af[mi][0], af[mi][1], af[mi][2], af[mi][3], a_base + SWZ(off));
            }
            uint32_t bf_[4][4];
            #pragma unroll
            for (int nj = 0; nj < 4; ++nj) {
                uint32_t off = (uint32_t)((wn * 64 + nj * 16 + (lane & 7) + ((lane >> 4) << 3)) * 128 +
                                          (k0 + (((lane >> 3) & 1) << 3)) * 2);
                LDSM_X4(bf_[nj][0], bf_[nj][1], bf_[nj][2], bf_[nj][3], b_base + SWZ(off));
            }
            #pragma unroll
            for (int mi = 0; mi < 2; ++mi)
                #pragma unroll
                for (int nj = 0; nj < 4; ++nj) {
                    MMA_F16(acc[mi][nj * 2],     af[mi], &bf_[nj][0]);
                    MMA_F16(acc[mi][nj * 2 + 1], af[mi], &bf_[nj][2]);
                }
        }
        __syncthreads();
    }
#undef LOADC

    const int group = lane >> 2, tig = lane & 3;
    if (Vout != nullptr && m0 >= 512) {
        // V rows: write fp16 to Vout [c][4096]
        __half* vb = Vout + (size_t)blockIdx.z * CC * 4096;
        #pragma unroll
        for (int mi = 0; mi < 2; ++mi)
            #pragma unroll
            for (int ni = 0; ni < 8; ++ni) {
                int row = m0 + wm * 32 + mi * 16 + group;
                int col = n0 + wn * 64 + ni * 8 + tig * 2;
                #pragma unroll
                for (int half_ = 0; half_ < 2; ++half_) {
                    int rr = row + half_ * 8;
                    __half2 hh;
                    hh.x = __float2half_rn(acc[mi][ni][half_ * 2]);
                    hh.y = __float2half_rn(acc[mi][ni][half_ * 2 + 1]);
                    *(__half2*)&vb[(size_t)(rr - 512) * 4096 + col] = hh;
                }
            }
    } else {
        #pragma unroll
        for (int mi = 0; mi < 2; ++mi)
            #pragma unroll
            for (int ni = 0; ni < 8; ++ni) {
                int row = m0 + wm * 32 + mi * 16 + group;
                int col = n0 + wn * 64 + ni * 8 + tig * 2;
                *(float2*)&C[(size_t)row * ldc + col]       = make_float2(acc[mi][ni][0], acc[mi][ni][1]);
                *(float2*)&C[(size_t)(row + 8) * ldc + col] = make_float2(acc[mi][ni][2], acc[mi][ni][3]);
            }
    }
}

// ---------------- softmax: fp32 S row -> fp16 P row --------------------------
__global__ void softmax_kernel(const float* __restrict__ S, __half* __restrict__ P,
                               float scale) {
    const float* r = S + (size_t)blockIdx.x * NN;
    __half* prow = P + (size_t)blockIdx.x * 4096;
    const int t = threadIdx.x;
    float v[16];
    float m = -1e30f;
    #pragma unroll
    for (int i = 0; i < 16; ++i) { v[i] = r[i * 256 + t] * scale; m = fmaxf(m, v[i]); }
    __shared__ float red[8];
    const int lane = t & 31, wd = t >> 5;
    #pragma unroll
    for (int off = 16; off > 0; off >>= 1) m = fmaxf(m, __shfl_xor_sync(0xffffffffu, m, off));
    if (lane == 0) red[wd] = m;
    __syncthreads();
    m = red[0];
    #pragma unroll
    for (int w = 1; w < 8; ++w) m = fmaxf(m, red[w]);
    float s = 0.0f;
    #pragma unroll
    for (int i = 0; i < 16; ++i) { v[i] = expf(v[i] - m); s += v[i]; }
    #pragma unroll
    for (int off = 16; off > 0; off >>= 1) s += __shfl_xor_sync(0xffffffffu, s, off);
    __syncthreads();
    if (lane == 0) red[wd] = s;
    __syncthreads();
    s = 0.0f;
    #pragma unroll
    for (int w = 0; w < 8; ++w) s += red[w];
    const float inv = 1.0f / s;
    #pragma unroll
    for (int i = 0; i < 16; ++i)
        prow[i * 256 + t] = __float2half_rn(v[i] * inv);
}

// ---------------- final ELA multiply-add -------------------------------------
__global__ void ela_add_kernel(const float* __restrict__ x, float* __restrict__ out) {
    size_t i = (size_t)blockIdx.x * 256 + threadIdx.x;
    size_t i4 = i * 4;
    int w  = (int)(i4 & 63);
    int h  = (int)((i4 >> 6) & 63);
    size_t bc = i4 >> 12;
    float sh = g_xh[bc * 64 + h];
    const float* xwp = &g_xw[bc * 64 + w];
    float4 xv = ((const float4*)x)[i];
    float4 ov = ((float4*)out)[i];
    ov.x += xv.x * sh * xwp[0];
    ov.y += xv.y * sh * xwp[1];
    ov.z += xv.z * sh * xwp[2];
    ov.w += xv.w * sh * xwp[3];
    ((float4*)out)[i] = ov;
}

// ---------------- launch ------------------------------------------------------
extern "C" void kernel_launch(void* const* d_in, const int* in_sizes, int n_in,
                              void* d_out, int out_size) {
    const float* x      = (const float*)d_in[0];
    const float* w_qkv  = (const float*)d_in[1];
    const float* w1     = (const float*)d_in[2];
    const float* b1     = (const float*)d_in[3];
    const float* gamma  = (const float*)d_in[4];
    const float* beta   = (const float*)d_in[5];
    float* out = (float*)d_out;

    void *pqk32_v, *pS_v, *pyh_v, *pyw_v, *pqT_v, *pkT_v, *pv_v, *pP_v, *pwh_v, *pxT_v;
    cudaGetSymbolAddress(&pqk32_v, g_qk32);
    cudaGetSymbolAddress(&pS_v,    g_S);
    cudaGetSymbolAddress(&pyh_v,   g_yh);
    cudaGetSymbolAddress(&pyw_v,   g_yw);
    cudaGetSymbolAddress(&pqT_v,   g_qT);
    cudaGetSymbolAddress(&pkT_v,   g_kT);
    cudaGetSymbolAddress(&pv_v,    g_v);
    cudaGetSymbolAddress(&pP_v,    g_P);
    cudaGetSymbolAddress(&pwh_v,   g_wh);
    cudaGetSymbolAddress(&pxT_v,   g_xT);
    float* pqk32 = (float*)pqk32_v;
    float* pS    = (float*)pS_v;

    static const int HSMEM = 65536;
    cudaFuncSetAttribute(hmma_kernel, cudaFuncAttributeMaxDynamicSharedMemorySize, HSMEM);

    // 1) means + GN branches
    mean_kernel<<<BB * CC, 64>>>(x, (float*)pyh_v, (float*)pyw_v);
    gn_kernel<<<BB * 2, 256>>>(w1, b1, gamma, beta);

    // 2) operand prep for qkv GEMM
    conv_w_kernel<<<768, 256>>>(w_qkv);
    splitT_x_kernel<<<dim3(CC / 32, NN / 32, BB), dim3(32, 8)>>>(x);

    // 3) qkv = W_qkv @ x  (M=768, N=4096, K=256); V rows written fp16
    hmma_kernel<<<dim3(NN / 128, 768 / 128, BB), 256, HSMEM>>>(
        (const __half*)pwh_v, (const __half*)pxT_v, pqk32, (__half*)pv_v,
        256, 256, NN, 256, (size_t)0, (size_t)NN * 256, (size_t)512 * NN);

    // 4) transpose q,k to fp16 buffers
    convert_kernel<<<dim3(512 / 32, NN / 32, BB), dim3(32, 8)>>>(pqk32);

    // 5) S = q^T k  (M=N=4096, K=256)
    hmma_kernel<<<dim3(NN / 128, NN / 128, BB), 256, HSMEM>>>(
        (const __half*)pqT_v, (const __half*)pkT_v, pS, nullptr,
        256, 256, NN, 256, (size_t)NN * 256, (size_t)NN * 256, (size_t)NN * NN);

    // 6) softmax rows (scale 1/16) -> fp16 P
    softmax_kernel<<<BB * NN, 256>>>(pS, (__half*)pP_v, 0.0625f);

    // 7) O = V · P^T  (M=256, N=4096, K=4096)
    hmma_kernel<<<dim3(NN / 128, CC / 128, BB), 256, HSMEM>>>(
        (const __half*)pv_v, (const __half*)pP_v, out, nullptr,
        4096, 4096, NN, 4096, (size_t)CC * 4096, (size_t)NN * 4096, (size_t)CC * NN);

    // 8) out += x * xh * xw
    ela_add_kernel<<<(BB * CC * HH * WW / 4) / 256, 256>>>(x, out);
}

// round 11
// speedup vs baseline: 6.6018x; 1.0589x over previous
#include <cuda_runtime.h>
#include <cuda_fp16.h>
#include <math.h>
#include <stdint.h>

#define BB 8
#define CC 256
#define HH 64
#define WW 64
#define NN 4096
#define GROUPS 16

#define SWZ(off) ((off) ^ (((off) >> 3) & 0x70))

__device__ __forceinline__ uint32_t smem_to_u32(const void* p) {
    uint32_t a;
    asm("{ .reg .u64 t; cvta.to.shared.u64 t, %1; cvt.u32.u64 %0, t; }" : "=r"(a) : "l"(p));
    return a;
}

#define LDSM_X4(r0, r1, r2, r3, addr) \
    asm volatile("ldmatrix.sync.aligned.m8n8.x4.shared.b16 {%0,%1,%2,%3}, [%4];" \
                 : "=r"(r0), "=r"(r1), "=r"(r2), "=r"(r3) : "r"(addr))

#define MMA_F16(d, a, b) \
    asm volatile("mma.sync.aligned.m16n8k16.row.col.f32.f16.f16.f32 " \
                 "{%0,%1,%2,%3}, {%4,%5,%6,%7}, {%8,%9}, {%0,%1,%2,%3};" \
                 : "+f"((d)[0]), "+f"((d)[1]), "+f"((d)[2]), "+f"((d)[3]) \
                 : "r"((a)[0]), "r"((a)[1]), "r"((a)[2]), "r"((a)[3]), \
                   "r"((b)[0]), "r"((b)[1]))

#define CP_ASYNC16(dst, src) \
    asm volatile("cp.async.cg.shared.global [%0], [%1], 16;" :: "r"(dst), "l"(src))

// ---------------- scratch ----------------------------------------------------
__device__ float g_yh[BB * CC * HH];
__device__ float g_yw[BB * CC * WW];
__device__ float g_xh[BB * CC * HH];
__device__ float g_xw[BB * CC * WW];
__device__ __align__(256) float g_qk32[(size_t)BB * 512 * NN];           // fp32 q,k rows
__device__ __align__(256) __half g_S16[(size_t)BB * NN * NN];            // fp16 logits
__device__ __align__(256) __half g_wh [768 * 256];                       // W_qkv fp16
__device__ __align__(256) __half g_xT [(size_t)BB * NN * 256];           // x^T fp16
__device__ __align__(256) __half g_qT [(size_t)BB * NN * 256];           // q^T fp16 (scaled 1/16)
__device__ __align__(256) __half g_kT [(size_t)BB * NN * 256];           // k^T fp16
__device__ __align__(256) __half g_v  [(size_t)BB * CC * 4096];          // V fp16 (K-major)
__device__ __align__(256) __half g_P  [(size_t)BB * NN * 4096];          // P fp16

// ---------------- kernel 1: row & column means -------------------------------
__global__ void mean_kernel(const float* __restrict__ x,
                            float* __restrict__ yh, float* __restrict__ yw) {
    __shared__ float tile[64][65];
    const int bc = blockIdx.x;
    const float* xp = x + (size_t)bc * (HH * WW);
    const int t = threadIdx.x;
    float accw = 0.0f;
    #pragma unroll 8
    for (int h = 0; h < HH; ++h) { float v = xp[h * WW + t]; tile[h][t] = v; accw += v; }
    yw[(size_t)bc * WW + t] = accw * (1.0f / WW);
    __syncthreads();
    float acch = 0.0f;
    #pragma unroll 8
    for (int w = 0; w < WW; ++w) acch += tile[t][w];
    yh[(size_t)bc * HH + t] = acch * (1.0f / HH);
}

// ---------------- kernel 2: GN branch ----------------------------------------
__global__ void gn_kernel(const float* __restrict__ w1, const float* __restrict__ b1,
                          const float* __restrict__ gamma, const float* __restrict__ beta) {
    const int b  = blockIdx.x >> 1;
    const int br = blockIdx.x & 1;
    const float* y   = (br ? g_yw : g_yh) + (size_t)b * CC * 64;
    float*       out = (br ? g_xw : g_xh) + (size_t)b * CC * 64;
    const int d = threadIdx.x;
    __shared__ float ys[64][65];
    float acc[64];
    const float bias = b1[d];
    #pragma unroll
    for (int l = 0; l < 64; ++l) acc[l] = bias;
    for (int kc = 0; kc < 4; ++kc) {
        __syncthreads();
        #pragma unroll
        for (int i = 0; i < 16; ++i) {
            int idx = d + i * 256;
            int k = idx >> 6, l = idx & 63;
            ys[k][l] = y[(size_t)(kc * 64 + k) * 64 + l];
        }
        __syncthreads();
        #pragma unroll 4
        for (int k = 0; k < 64; ++k) {
            float wv = w1[(size_t)d * CC + kc * 64 + k];
            #pragma unroll
            for (int l = 0; l < 64; ++l) acc[l] += wv * ys[k][l];
        }
    }
    float s = 0.0f, s2 = 0.0f;
    #pragma unroll
    for (int l = 0; l < 64; ++l) { s += acc[l]; s2 += acc[l] * acc[l]; }
    #pragma unroll
    for (int off = 8; off > 0; off >>= 1) {
        s  += __shfl_down_sync(0xffffffffu, s,  off, 16);
        s2 += __shfl_down_sync(0xffffffffu, s2, off, 16);
    }
    s  = __shfl_sync(0xffffffffu, s,  0, 16);
    s2 = __shfl_sync(0xffffffffu, s2, 0, 16);
    const float mu  = s * (1.0f / 1024.0f);
    const float var = s2 * (1.0f / 1024.0f) - mu * mu;
    const float rstd = rsqrtf(var + 1e-5f);
    const float ga = gamma[d], be = beta[d];
    #pragma unroll
    for (int l = 0; l < 64; ++l) {
        float zn = (acc[l] - mu) * rstd;
        float tt = zn * ga + be;
        out[(size_t)d * 64 + l] = 1.0f / (1.0f + expf(-tt));
    }
}

// ---------------- W_qkv fp32 -> fp16 -----------------------------------------
__global__ void conv_w_kernel(const float* __restrict__ w) {
    int i = blockIdx.x * 256 + threadIdx.x;        // 768*256
    g_wh[i] = __float2half_rn(w[i]);
}

// ---------------- transpose x -> fp16 ----------------------------------------
__global__ void splitT_x_kernel(const float* __restrict__ x) {
    __shared__ float tile[32][33];
    const int c0 = blockIdx.x * 32, n0 = blockIdx.y * 32, b = blockIdx.z;
    const int tx = threadIdx.x, ty = threadIdx.y;
    const float* src = x + ((size_t)b * CC + c0) * NN + n0;
    #pragma unroll
    for (int i = 0; i < 4; ++i) tile[ty + 8 * i][tx] = src[(size_t)(ty + 8 * i) * NN + tx];
    __syncthreads();
    #pragma unroll
    for (int i = 0; i < 4; ++i) {
        int n = n0 + ty + 8 * i;
        g_xT[((size_t)b * NN + n) * 256 + c0 + tx] = __float2half_rn(tile[tx][ty + 8 * i]);
    }
}

// ---------------- q,k fp32 -> fp16 transposed (q scaled by 1/16) -------------
__global__ void convert_kernel(const float* __restrict__ qk) {
    __shared__ float tile[32][33];
    const int d0 = blockIdx.x * 32, n0 = blockIdx.y * 32, b = blockIdx.z;
    const int tx = threadIdx.x, ty = threadIdx.y;
    const float* src = qk + ((size_t)b * 512 + d0) * NN + n0;
    #pragma unroll
    for (int i = 0; i < 4; ++i) tile[ty + 8 * i][tx] = src[(size_t)(ty + 8 * i) * NN + tx];
    __syncthreads();
    const bool isq = (d0 < 256);
    __half* dst = isq ? g_qT : g_kT;
    const float sc = isq ? 0.0625f : 1.0f;
    const int dd0 = d0 & 255;
    #pragma unroll
    for (int i = 0; i < 4; ++i) {
        int n = n0 + ty + 8 * i;
        dst[((size_t)b * NN + n) * 256 + dd0 + tx] =
            __float2half_rn(tile[tx][ty + 8 * i] * sc);
    }
}

// ---------------- fp16 mma.sync GEMM: C[m][n] = Σ_k A[m][k] B[n][k] ----------
// 3-stage cp.async pipeline (prefetch distance 2), one __syncthreads per chunk.
// Epilogue modes: Vout (qkv: rows >= 512 as fp16 V), Hout (fp16 full tile),
// else fp32 C.
__global__ __launch_bounds__(256, 2)
void hmma_kernel(const __half* __restrict__ A, const __half* __restrict__ B,
                 float* __restrict__ C, __half* __restrict__ Hout,
                 __half* __restrict__ Vout,
                 int lda, int ldb, int ldc, int K,
                 size_t sA, size_t sB, size_t sC) {
    extern __shared__ char smem[];
    const uint32_t sb = smem_to_u32(smem);
    const int tid = threadIdx.x, lane = tid & 31, wid = tid >> 5;
    const int wm = wid & 3, wn = wid >> 2;
    A += (size_t)blockIdx.z * sA;
    B += (size_t)blockIdx.z * sB;
    const int m0 = blockIdx.y * 128, n0 = blockIdx.x * 128;
    const int nch = K >> 6;

    float acc[2][8][4];
    #pragma unroll
    for (int mi = 0; mi < 2; ++mi)
        #pragma unroll
        for (int ni = 0; ni < 8; ++ni)
            #pragma unroll
            for (int q = 0; q < 4; ++q) acc[mi][ni][q] = 0.0f;

    // stage s: A at s*32768, B at s*32768 + 16384
#define LOADC(j, st) do {                                                                \
    int k0_ = (j) * 64;                                                                  \
    uint32_t ab = sb + (uint32_t)(st) * 32768u;                                          \
    uint32_t bb = ab + 16384u;                                                           \
    _Pragma("unroll")                                                                    \
    for (int it = 0; it < 4; ++it) {                                                     \
        int id = tid + it * 256; int r = id >> 3, c8 = id & 7;                           \
        CP_ASYNC16(ab + SWZ((uint32_t)(r * 128 + c8 * 16)),                              \
                   A + (size_t)(m0 + r) * lda + k0_ + c8 * 8);                           \
        CP_ASYNC16(bb + SWZ((uint32_t)(r * 128 + c8 * 16)),                              \
                   B + (size_t)(n0 + r) * ldb + k0_ + c8 * 8);                           \
    }                                                                                    \
    asm volatile("cp.async.commit_group;");                                              \
} while (0)

    LOADC(0, 0);
    if (nch > 1) LOADC(1, 1);
    for (int j = 0; j < nch; ++j) {
        if (j + 1 < nch) asm volatile("cp.async.wait_group 1;");
        else             asm volatile("cp.async.wait_group 0;");
        __syncthreads();
        if (j + 2 < nch) LOADC(j + 2, (j + 2) % 3);
        const uint32_t a_base = sb + (uint32_t)(j % 3) * 32768u;
        const uint32_t b_base = a_base + 16384u;
        #pragma unroll
        for (int ks = 0; ks < 4; ++ks) {
            const int k0 = ks * 16;
            uint32_t af[2][4];
            #pragma unroll
            for (int mi = 0; mi < 2; ++mi) {
                uint32_t off = (uint32_t)((wm * 32 + mi * 16 + (lane & 15)) * 128 +
                                          (k0 + ((lane >> 4) << 3)) * 2);
                LDSM_X4(af[mi][0], af[mi][1], af[mi][2], af[mi][3], a_base + SWZ(off));
            }
            uint32_t bf_[4][4];
            #pragma unroll
            for (int nj = 0; nj < 4; ++nj) {
                uint32_t off = (uint32_t)((wn * 64 + nj * 16 + (lane & 7) + ((lane >> 4) << 3)) * 128 +
                                          (k0 + (((lane >> 3) & 1) << 3)) * 2);
                LDSM_X4(bf_[nj][0], bf_[nj][1], bf_[nj][2], bf_[nj][3], b_base + SWZ(off));
            }
            #pragma unroll
            for (int mi = 0; mi < 2; ++mi)
                #pragma unroll
                for (int nj = 0; nj < 4; ++nj) {
                    MMA_F16(acc[mi][nj * 2],     af[mi], &bf_[nj][0]);
                    MMA_F16(acc[mi][nj * 2 + 1], af[mi], &bf_[nj][2]);
                }
        }
    }
#undef LOADC

    const int group = lane >> 2, tig = lane & 3;
    if (Vout != nullptr && m0 >= 512) {
        // V rows: write fp16 to Vout [c][4096]
        __half* vb = Vout + (size_t)blockIdx.z * CC * 4096;
        #pragma unroll
        for (int mi = 0; mi < 2; ++mi)
            #pragma unroll
            for (int ni = 0; ni < 8; ++ni) {
                int row = m0 + wm * 32 + mi * 16 + group;
                int col = n0 + wn * 64 + ni * 8 + tig * 2;
                #pragma unroll
                for (int half_ = 0; half_ < 2; ++half_) {
                    int rr = row + half_ * 8;
                    __half2 hh;
                    hh.x = __float2half_rn(acc[mi][ni][half_ * 2]);
                    hh.y = __float2half_rn(acc[mi][ni][half_ * 2 + 1]);
                    *(__half2*)&vb[(size_t)(rr - 512) * 4096 + col] = hh;
                }
            }
    } else if (Hout != nullptr) {
        __half* hb = Hout + (size_t)blockIdx.z * sC;
        #pragma unroll
        for (int mi = 0; mi < 2; ++mi)
            #pragma unroll
            for (int ni = 0; ni < 8; ++ni) {
                int row = m0 + wm * 32 + mi * 16 + group;
                int col = n0 + wn * 64 + ni * 8 + tig * 2;
                #pragma unroll
                for (int half_ = 0; half_ < 2; ++half_) {
                    int rr = row + half_ * 8;
                    __half2 hh;
                    hh.x = __float2half_rn(acc[mi][ni][half_ * 2]);
                    hh.y = __float2half_rn(acc[mi][ni][half_ * 2 + 1]);
                    *(__half2*)&hb[(size_t)rr * ldc + col] = hh;
                }
            }
    } else {
        float* cb = C + (size_t)blockIdx.z * sC;
        #pragma unroll
        for (int mi = 0; mi < 2; ++mi)
            #pragma unroll
            for (int ni = 0; ni < 8; ++ni) {
                int row = m0 + wm * 32 + mi * 16 + group;
                int col = n0 + wn * 64 + ni * 8 + tig * 2;
                *(float2*)&cb[(size_t)row * ldc + col]       = make_float2(acc[mi][ni][0], acc[mi][ni][1]);
                *(float2*)&cb[(size_t)(row + 8) * ldc + col] = make_float2(acc[mi][ni][2], acc[mi][ni][3]);
            }
    }
}

// ---------------- softmax: fp16 logits row -> fp16 P row ---------------------
__global__ void softmax_kernel(const __half* __restrict__ S, __half* __restrict__ P) {
    const __half* r = S + (size_t)blockIdx.x * NN;
    __half* prow = P + (size_t)blockIdx.x * 4096;
    const int t = threadIdx.x;
    float v[16];
    float m = -1e30f;
    #pragma unroll
    for (int i = 0; i < 16; ++i) { v[i] = __half2float(r[i * 256 + t]); m = fmaxf(m, v[i]); }
    __shared__ float red[8];
    const int lane = t & 31, wd = t >> 5;
    #pragma unroll
    for (int off = 16; off > 0; off >>= 1) m = fmaxf(m, __shfl_xor_sync(0xffffffffu, m, off));
    if (lane == 0) red[wd] = m;
    __syncthreads();
    m = red[0];
    #pragma unroll
    for (int w = 1; w < 8; ++w) m = fmaxf(m, red[w]);
    float s = 0.0f;
    #pragma unroll
    for (int i = 0; i < 16; ++i) { v[i] = expf(v[i] - m); s += v[i]; }
    #pragma unroll
    for (int off = 16; off > 0; off >>= 1) s += __shfl_xor_sync(0xffffffffu, s, off);
    __syncthreads();
    if (lane == 0) red[wd] = s;
    __syncthreads();
    s = 0.0f;
    #pragma unroll
    for (int w = 0; w < 8; ++w) s += red[w];
    const float inv = 1.0f / s;
    #pragma unroll
    for (int i = 0; i < 16; ++i)
        prow[i * 256 + t] = __float2half_rn(v[i] * inv);
}

// ---------------- final ELA multiply-add -------------------------------------
__global__ void ela_add_kernel(const float* __restrict__ x, float* __restrict__ out) {
    size_t i = (size_t)blockIdx.x * 256 + threadIdx.x;
    size_t i4 = i * 4;
    int w  = (int)(i4 & 63);
    int h  = (int)((i4 >> 6) & 63);
    size_t bc = i4 >> 12;
    float sh = g_xh[bc * 64 + h];
    const float* xwp = &g_xw[bc * 64 + w];
    float4 xv = ((const float4*)x)[i];
    float4 ov = ((float4*)out)[i];
    ov.x += xv.x * sh * xwp[0];
    ov.y += xv.y * sh * xwp[1];
    ov.z += xv.z * sh * xwp[2];
    ov.w += xv.w * sh * xwp[3];
    ((float4*)out)[i] = ov;
}

// ---------------- launch ------------------------------------------------------
extern "C" void kernel_launch(void* const* d_in, const int* in_sizes, int n_in,
                              void* d_out, int out_size) {
    const float* x      = (const float*)d_in[0];
    const float* w_qkv  = (const float*)d_in[1];
    const float* w1     = (const float*)d_in[2];
    const float* b1     = (const float*)d_in[3];
    const float* gamma  = (const float*)d_in[4];
    const float* beta   = (const float*)d_in[5];
    float* out = (float*)d_out;

    void *pqk32_v, *pS16_v, *pyh_v, *pyw_v, *pqT_v, *pkT_v, *pv_v, *pP_v, *pwh_v, *pxT_v;
    cudaGetSymbolAddress(&pqk32_v, g_qk32);
    cudaGetSymbolAddress(&pS16_v,  g_S16);
    cudaGetSymbolAddress(&pyh_v,   g_yh);
    cudaGetSymbolAddress(&pyw_v,   g_yw);
    cudaGetSymbolAddress(&pqT_v,   g_qT);
    cudaGetSymbolAddress(&pkT_v,   g_kT);
    cudaGetSymbolAddress(&pv_v,    g_v);
    cudaGetSymbolAddress(&pP_v,    g_P);
    cudaGetSymbolAddress(&pwh_v,   g_wh);
    cudaGetSymbolAddress(&pxT_v,   g_xT);
    float* pqk32 = (float*)pqk32_v;

    static const int HSMEM = 98304;   // 3 stages x (16KB A + 16KB B)
    cudaFuncSetAttribute(hmma_kernel, cudaFuncAttributeMaxDynamicSharedMemorySize, HSMEM);

    // 1) means + GN branches
    mean_kernel<<<BB * CC, 64>>>(x, (float*)pyh_v, (float*)pyw_v);
    gn_kernel<<<BB * 2, 256>>>(w1, b1, gamma, beta);

    // 2) operand prep for qkv GEMM
    conv_w_kernel<<<768, 256>>>(w_qkv);
    splitT_x_kernel<<<dim3(CC / 32, NN / 32, BB), dim3(32, 8)>>>(x);

    // 3) qkv = W_qkv @ x  (M=768, N=4096, K=256); V rows written fp16
    hmma_kernel<<<dim3(NN / 128, 768 / 128, BB), 256, HSMEM>>>(
        (const __half*)pwh_v, (const __half*)pxT_v, pqk32, nullptr, (__half*)pv_v,
        256, 256, NN, 256, (size_t)0, (size_t)NN * 256, (size_t)512 * NN);

    // 4) transpose q,k to fp16 buffers (q scaled by 1/16)
    convert_kernel<<<dim3(512 / 32, NN / 32, BB), dim3(32, 8)>>>(pqk32);

    // 5) logits = q^T k (scale folded into q) -> fp16 S
    hmma_kernel<<<dim3(NN / 128, NN / 128, BB), 256, HSMEM>>>(
        (const __half*)pqT_v, (const __half*)pkT_v, nullptr, (__half*)pS16_v, nullptr,
        256, 256, NN, 256, (size_t)NN * 256, (size_t)NN * 256, (size_t)NN * NN);

    // 6) softmax rows -> fp16 P
    softmax_kernel<<<BB * NN, 256>>>((const __half*)pS16_v, (__half*)pP_v);

    // 7) O = V · P^T  (M=256, N=4096, K=4096)
    hmma_kernel<<<dim3(NN / 128, CC / 128, BB), 256, HSMEM>>>(
        (const __half*)pv_v, (const __half*)pP_v, out, nullptr, nullptr,
        4096, 4096, NN, 4096, (size_t)CC * 4096, (size_t)NN * 4096, (size_t)CC * NN);

    // 8) out += x * xh * xw
    ela_add_kernel<<<(BB * CC * HH * WW / 4) / 256, 256>>>(x, out);
}

// round 14
// speedup vs baseline: 6.9171x; 1.0478x over previous
#include <cuda_runtime.h>
#include <cuda_fp16.h>
#include <math.h>
#include <stdint.h>

#define BB 8
#define CC 256
#define HH 64
#define WW 64
#define NN 4096
#define GROUPS 16

#define SWZ(off) ((off) ^ (((off) >> 3) & 0x70))

__device__ __forceinline__ uint32_t smem_to_u32(const void* p) {
    uint32_t a;
    asm("{ .reg .u64 t; cvta.to.shared.u64 t, %1; cvt.u32.u64 %0, t; }" : "=r"(a) : "l"(p));
    return a;
}

#define LDSM_X4(r0, r1, r2, r3, addr) \
    asm volatile("ldmatrix.sync.aligned.m8n8.x4.shared.b16 {%0,%1,%2,%3}, [%4];" \
                 : "=r"(r0), "=r"(r1), "=r"(r2), "=r"(r3) : "r"(addr))

#define MMA_F16(d, a, b) \
    asm volatile("mma.sync.aligned.m16n8k16.row.col.f32.f16.f16.f32 " \
                 "{%0,%1,%2,%3}, {%4,%5,%6,%7}, {%8,%9}, {%0,%1,%2,%3};" \
                 : "+f"((d)[0]), "+f"((d)[1]), "+f"((d)[2]), "+f"((d)[3]) \
                 : "r"((a)[0]), "r"((a)[1]), "r"((a)[2]), "r"((a)[3]), \
                   "r"((b)[0]), "r"((b)[1]))

#define CP_ASYNC16(dst, src) \
    asm volatile("cp.async.cg.shared.global [%0], [%1], 16;" :: "r"(dst), "l"(src))

// ---------------- scratch ----------------------------------------------------
__device__ float g_yh[BB * CC * HH];
__device__ float g_yw[BB * CC * WW];
__device__ float g_xh[BB * CC * HH];
__device__ float g_xw[BB * CC * WW];
__device__ __align__(256) __half g_S16[(size_t)BB * NN * NN];            // fp16 logits
__device__ __align__(256) __half g_wh [768 * 256];                       // W_qkv fp16
__device__ __align__(256) __half g_xT [(size_t)BB * NN * 256];           // x^T fp16
__device__ __align__(256) __half g_qT [(size_t)BB * NN * 256];           // q^T fp16 (scaled 1/16)
__device__ __align__(256) __half g_kT [(size_t)BB * NN * 256];           // k^T fp16
__device__ __align__(256) __half g_v  [(size_t)BB * CC * 4096];          // V fp16 (K-major)
__device__ __align__(256) __half g_P  [(size_t)BB * NN * 4096];          // P fp16

// ---------------- kernel 1: row & column means -------------------------------
__global__ void mean_kernel(const float* __restrict__ x,
                            float* __restrict__ yh, float* __restrict__ yw) {
    __shared__ float tile[64][65];
    const int bc = blockIdx.x;
    const float* xp = x + (size_t)bc * (HH * WW);
    const int t = threadIdx.x;
    float accw = 0.0f;
    #pragma unroll 8
    for (int h = 0; h < HH; ++h) { float v = xp[h * WW + t]; tile[h][t] = v; accw += v; }
    yw[(size_t)bc * WW + t] = accw * (1.0f / WW);
    __syncthreads();
    float acch = 0.0f;
    #pragma unroll 8
    for (int w = 0; w < WW; ++w) acch += tile[t][w];
    yh[(size_t)bc * HH + t] = acch * (1.0f / HH);
}

// ---------------- kernel 2: GN branch ----------------------------------------
__global__ void gn_kernel(const float* __restrict__ w1, const float* __restrict__ b1,
                          const float* __restrict__ gamma, const float* __restrict__ beta) {
    const int b  = blockIdx.x >> 1;
    const int br = blockIdx.x & 1;
    const float* y   = (br ? g_yw : g_yh) + (size_t)b * CC * 64;
    float*       out = (br ? g_xw : g_xh) + (size_t)b * CC * 64;
    const int d = threadIdx.x;
    __shared__ float ys[64][65];
    float acc[64];
    const float bias = b1[d];
    #pragma unroll
    for (int l = 0; l < 64; ++l) acc[l] = bias;
    for (int kc = 0; kc < 4; ++kc) {
        __syncthreads();
        #pragma unroll
        for (int i = 0; i < 16; ++i) {
            int idx = d + i * 256;
            int k = idx >> 6, l = idx & 63;
            ys[k][l] = y[(size_t)(kc * 64 + k) * 64 + l];
        }
        __syncthreads();
        #pragma unroll 4
        for (int k = 0; k < 64; ++k) {
            float wv = w1[(size_t)d * CC + kc * 64 + k];
            #pragma unroll
            for (int l = 0; l < 64; ++l) acc[l] += wv * ys[k][l];
        }
    }
    float s = 0.0f, s2 = 0.0f;
    #pragma unroll
    for (int l = 0; l < 64; ++l) { s += acc[l]; s2 += acc[l] * acc[l]; }
    #pragma unroll
    for (int off = 8; off > 0; off >>= 1) {
        s  += __shfl_down_sync(0xffffffffu, s,  off, 16);
        s2 += __shfl_down_sync(0xffffffffu, s2, off, 16);
    }
    s  = __shfl_sync(0xffffffffu, s,  0, 16);
    s2 = __shfl_sync(0xffffffffu, s2, 0, 16);
    const float mu  = s * (1.0f / 1024.0f);
    const float var = s2 * (1.0f / 1024.0f) - mu * mu;
    const float rstd = rsqrtf(var + 1e-5f);
    const float ga = gamma[d], be = beta[d];
    #pragma unroll
    for (int l = 0; l < 64; ++l) {
        float zn = (acc[l] - mu) * rstd;
        float tt = zn * ga + be;
        out[(size_t)d * 64 + l] = 1.0f / (1.0f + expf(-tt));
    }
}

// ---------------- W_qkv fp32 -> fp16 -----------------------------------------
__global__ void conv_w_kernel(const float* __restrict__ w) {
    int i = blockIdx.x * 256 + threadIdx.x;        // 768*256
    g_wh[i] = __float2half_rn(w[i]);
}

// ---------------- transpose x -> fp16 ----------------------------------------
__global__ void splitT_x_kernel(const float* __restrict__ x) {
    __shared__ float tile[32][33];
    const int c0 = blockIdx.x * 32, n0 = blockIdx.y * 32, b = blockIdx.z;
    const int tx = threadIdx.x, ty = threadIdx.y;
    const float* src = x + ((size_t)b * CC + c0) * NN + n0;
    #pragma unroll
    for (int i = 0; i < 4; ++i) tile[ty + 8 * i][tx] = src[(size_t)(ty + 8 * i) * NN + tx];
    __syncthreads();
    #pragma unroll
    for (int i = 0; i < 4; ++i) {
        int n = n0 + ty + 8 * i;
        g_xT[((size_t)b * NN + n) * 256 + c0 + tx] = __float2half_rn(tile[tx][ty + 8 * i]);
    }
}

// ---------------- fp16 mma.sync GEMM: C[m][n] = Σ_k A[m][k] B[n][k] ----------
// 3-stage cp.async pipeline, one __syncthreads per chunk.
// mode 1: fp16 tile -> Hout (ldc)
// mode 2: qkv special — q rows (m0<256) -> g_qT transposed, scaled 1/16;
//         k rows (256..512) -> g_kT transposed; v rows (>=512) -> g_v K-major.
// mode 3: fp32 out = acc + x*xh*xw (ELA fused), -> Cout (ldc)
__global__ __launch_bounds__(256, 2)
void hmma_kernel(const __half* __restrict__ A, const __half* __restrict__ B,
                 void* __restrict__ outp, const float* __restrict__ Xin,
                 int lda, int ldb, int ldc, int K,
                 size_t sA, size_t sB, size_t sC, int mode) {
    extern __shared__ char smem[];
    const uint32_t sb = smem_to_u32(smem);
    const int tid = threadIdx.x, lane = tid & 31, wid = tid >> 5;
    const int wm = wid & 3, wn = wid >> 2;
    const int z = blockIdx.z;
    A += (size_t)z * sA;
    B += (size_t)z * sB;
    const int m0 = blockIdx.y * 128, n0 = blockIdx.x * 128;
    const int nch = K >> 6;

    float acc[2][8][4];
    #pragma unroll
    for (int mi = 0; mi < 2; ++mi)
        #pragma unroll
        for (int ni = 0; ni < 8; ++ni)
            #pragma unroll
            for (int q = 0; q < 4; ++q) acc[mi][ni][q] = 0.0f;

#define LOADC(j, st) do {                                                                \
    int k0_ = (j) * 64;                                                                  \
    uint32_t ab = sb + (uint32_t)(st) * 32768u;                                          \
    uint32_t bb = ab + 16384u;                                                           \
    _Pragma("unroll")                                                                    \
    for (int it = 0; it < 4; ++it) {                                                     \
        int id = tid + it * 256; int r = id >> 3, c8 = id & 7;                           \
        CP_ASYNC16(ab + SWZ((uint32_t)(r * 128 + c8 * 16)),                              \
                   A + (size_t)(m0 + r) * lda + k0_ + c8 * 8);                           \
        CP_ASYNC16(bb + SWZ((uint32_t)(r * 128 + c8 * 16)),                              \
                   B + (size_t)(n0 + r) * ldb + k0_ + c8 * 8);                           \
    }                                                                                    \
    asm volatile("cp.async.commit_group;");                                              \
} while (0)

    LOADC(0, 0);
    if (nch > 1) LOADC(1, 1);
    for (int j = 0; j < nch; ++j) {
        if (j + 1 < nch) asm volatile("cp.async.wait_group 1;");
        else             asm volatile("cp.async.wait_group 0;");
        __syncthreads();
        if (j + 2 < nch) LOADC(j + 2, (j + 2) % 3);
        const uint32_t a_base = sb + (uint32_t)(j % 3) * 32768u;
        const uint32_t b_base = a_base + 16384u;
        #pragma unroll
        for (int ks = 0; ks < 4; ++ks) {
            const int k0 = ks * 16;
            uint32_t af[2][4];
            #pragma unroll
            for (int mi = 0; mi < 2; ++mi) {
                uint32_t off = (uint32_t)((wm * 32 + mi * 16 + (lane & 15)) * 128 +
                                          (k0 + ((lane >> 4) << 3)) * 2);
                LDSM_X4(af[mi][0], af[mi][1], af[mi][2], af[mi][3], a_base + SWZ(off));
            }
            uint32_t bf_[4][4];
            #pragma unroll
            for (int nj = 0; nj < 4; ++nj) {
                uint32_t off = (uint32_t)((wn * 64 + nj * 16 + (lane & 7) + ((lane >> 4) << 3)) * 128 +
                                          (k0 + (((lane >> 3) & 1) << 3)) * 2);
                LDSM_X4(bf_[nj][0], bf_[nj][1], bf_[nj][2], bf_[nj][3], b_base + SWZ(off));
            }
            #pragma unroll
            for (int mi = 0; mi < 2; ++mi)
                #pragma unroll
                for (int nj = 0; nj < 4; ++nj) {
                    MMA_F16(acc[mi][nj * 2],     af[mi], &bf_[nj][0]);
                    MMA_F16(acc[mi][nj * 2 + 1], af[mi], &bf_[nj][2]);
                }
        }
    }
#undef LOADC

    const int group = lane >> 2, tig = lane & 3;
    if (mode == 2) {
        if (m0 < 512) {
            // q/k rows: transpose via smem, write fp16 [n][256]
            const bool isq = (m0 < 256);
            const float sc = isq ? 0.0625f : 1.0f;
            __half* dstg = isq ? g_qT : g_kT;
            const int d_base = isq ? m0 : (m0 - 256);
            __half* st = (__half*)smem;          // [128 cols n][136 rows d]
            __syncthreads();                     // smem reuse after pipeline
            #pragma unroll
            for (int mi = 0; mi < 2; ++mi)
                #pragma unroll
                for (int ni = 0; ni < 8; ++ni) {
                    int rl = wm * 32 + mi * 16 + group;
                    int cl = wn * 64 + ni * 8 + tig * 2;
                    st[(cl)     * 136 + rl]     = __float2half_rn(acc[mi][ni][0] * sc);
                    st[(cl + 1) * 136 + rl]     = __float2half_rn(acc[mi][ni][1] * sc);
                    st[(cl)     * 136 + rl + 8] = __float2half_rn(acc[mi][ni][2] * sc);
                    st[(cl + 1) * 136 + rl + 8] = __float2half_rn(acc[mi][ni][3] * sc);
                }
            __syncthreads();
            #pragma unroll
            for (int it = 0; it < 8; ++it) {
                int nl = it * 16 + (tid >> 4);
                int dseg = tid & 15;
                uint4 val = *(uint4*)&st[nl * 136 + dseg * 8];
                *(uint4*)&dstg[((size_t)z * NN + n0 + nl) * 256 + d_base + dseg * 8] = val;
            }
        } else {
            // V rows: fp16 K-major [c][4096]
            __half* vb = g_v + (size_t)z * CC * 4096;
            #pragma unroll
            for (int mi = 0; mi < 2; ++mi)
                #pragma unroll
                for (int ni = 0; ni < 8; ++ni) {
                    int row = m0 + wm * 32 + mi * 16 + group;
                    int col = n0 + wn * 64 + ni * 8 + tig * 2;
                    #pragma unroll
                    for (int hf = 0; hf < 2; ++hf) {
                        int rr = row + hf * 8;
                        __half2 hh;
                        hh.x = __float2half_rn(acc[mi][ni][hf * 2]);
                        hh.y = __float2half_rn(acc[mi][ni][hf * 2 + 1]);
                        *(__half2*)&vb[(size_t)(rr - 512) * 4096 + col] = hh;
                    }
                }
        }
    } else if (mode == 1) {
        __half* hb = (__half*)outp + (size_t)z * sC;
        #pragma unroll
        for (int mi = 0; mi < 2; ++mi)
            #pragma unroll
            for (int ni = 0; ni < 8; ++ni) {
                int row = m0 + wm * 32 + mi * 16 + group;
                int col = n0 + wn * 64 + ni * 8 + tig * 2;
                #pragma unroll
                for (int hf = 0; hf < 2; ++hf) {
                    int rr = row + hf * 8;
                    __half2 hh;
                    hh.x = __float2half_rn(acc[mi][ni][hf * 2]);
                    hh.y = __float2half_rn(acc[mi][ni][hf * 2 + 1]);
                    *(__half2*)&hb[(size_t)rr * ldc + col] = hh;
                }
            }
    } else {
        // mode 3: fp32 out = acc + x*xh*xw
        float* cb = (float*)outp + (size_t)z * sC;
        const float* xb = Xin + (size_t)z * CC * NN;
        #pragma unroll
        for (int mi = 0; mi < 2; ++mi)
            #pragma unroll
            for (int ni = 0; ni < 8; ++ni) {
                int row = m0 + wm * 32 + mi * 16 + group;
                int col = n0 + wn * 64 + ni * 8 + tig * 2;
                int hcol = col >> 6, wcol = col & 63;
                #pragma unroll
                for (int hf = 0; hf < 2; ++hf) {
                    int rr = row + hf * 8;
                    size_t sidx = ((size_t)z * CC + rr) * 64;
                    float sh = g_xh[sidx + hcol];
                    float w0 = g_xw[sidx + wcol];
                    float w1 = g_xw[sidx + wcol + 1];
                    float2 xv = *(const float2*)&xb[(size_t)rr * NN + col];
                    float2 ov;
                    ov.x = acc[mi][ni][hf * 2]     + xv.x * sh * w0;
                    ov.y = acc[mi][ni][hf * 2 + 1] + xv.y * sh * w1;
                    *(float2*)&cb[(size_t)rr * ldc + col] = ov;
                }
            }
    }
}

// ---------------- softmax: fp16 logits row -> fp16 P row (vectorized) --------
__global__ void softmax_kernel(const __half* __restrict__ S, __half* __restrict__ P) {
    const uint4* rp = (const uint4*)(S + (size_t)blockIdx.x * NN);
    uint4* pp = (uint4*)(P + (size_t)blockIdx.x * 4096);
    const int t = threadIdx.x;
    uint4 u0 = rp[t], u1 = rp[t + 256];
    float v[16];
    {
        const uint32_t* w0 = (const uint32_t*)&u0;
        const uint32_t* w1 = (const uint32_t*)&u1;
        #pragma unroll
        for (int i = 0; i < 4; ++i) {
            float2 f0 = __half22float2(*(const __half2*)&w0[i]);
            float2 f1 = __half22float2(*(const __half2*)&w1[i]);
            v[i * 2]     = f0.x; v[i * 2 + 1] = f0.y;
            v[8 + i * 2] = f1.x; v[8 + i * 2 + 1] = f1.y;
        }
    }
    float m = v[0];
    #pragma unroll
    for (int i = 1; i < 16; ++i) m = fmaxf(m, v[i]);
    __shared__ float red[8];
    const int lane = t & 31, wd = t >> 5;
    #pragma unroll
    for (int off = 16; off > 0; off >>= 1) m = fmaxf(m, __shfl_xor_sync(0xffffffffu, m, off));
    if (lane == 0) red[wd] = m;
    __syncthreads();
    m = red[0];
    #pragma unroll
    for (int w = 1; w < 8; ++w) m = fmaxf(m, red[w]);
    float s = 0.0f;
    #pragma unroll
    for (int i = 0; i < 16; ++i) { v[i] = expf(v[i] - m); s += v[i]; }
    #pragma unroll
    for (int off = 16; off > 0; off >>= 1) s += __shfl_xor_sync(0xffffffffu, s, off);
    __syncthreads();
    if (lane == 0) red[wd] = s;
    __syncthreads();
    s = 0.0f;
    #pragma unroll
    for (int w = 0; w < 8; ++w) s += red[w];
    const float inv = 1.0f / s;
    uint4 o0, o1;
    {
        uint32_t* w0 = (uint32_t*)&o0;
        uint32_t* w1 = (uint32_t*)&o1;
        #pragma unroll
        for (int i = 0; i < 4; ++i) {
            __half2 h0 = __floats2half2_rn(v[i * 2] * inv, v[i * 2 + 1] * inv);
            __half2 h1 = __floats2half2_rn(v[8 + i * 2] * inv, v[8 + i * 2 + 1] * inv);
            w0[i] = *(uint32_t*)&h0;
            w1[i] = *(uint32_t*)&h1;
        }
    }
    pp[t] = o0;
    pp[t + 256] = o1;
}

// ---------------- launch ------------------------------------------------------
extern "C" void kernel_launch(void* const* d_in, const int* in_sizes, int n_in,
                              void* d_out, int out_size) {
    const float* x      = (const float*)d_in[0];
    const float* w_qkv  = (const float*)d_in[1];
    const float* w1     = (const float*)d_in[2];
    const float* b1     = (const float*)d_in[3];
    const float* gamma  = (const float*)d_in[4];
    const float* beta   = (const float*)d_in[5];
    float* out = (float*)d_out;

    void *pS16_v, *pyh_v, *pyw_v, *pqT_v, *pkT_v, *pv_v, *pP_v, *pwh_v, *pxT_v;
    cudaGetSymbolAddress(&pS16_v,  g_S16);
    cudaGetSymbolAddress(&pyh_v,   g_yh);
    cudaGetSymbolAddress(&pyw_v,   g_yw);
    cudaGetSymbolAddress(&pqT_v,   g_qT);
    cudaGetSymbolAddress(&pkT_v,   g_kT);
    cudaGetSymbolAddress(&pv_v,    g_v);
    cudaGetSymbolAddress(&pP_v,    g_P);
    cudaGetSymbolAddress(&pwh_v,   g_wh);
    cudaGetSymbolAddress(&pxT_v,   g_xT);

    static const int HSMEM = 98304;   // 3 stages x (16KB A + 16KB B); epilogue reuses
    cudaFuncSetAttribute(hmma_kernel, cudaFuncAttributeMaxDynamicSharedMemorySize, HSMEM);

    // 1) means + GN branches
    mean_kernel<<<BB * CC, 64>>>(x, (float*)pyh_v, (float*)pyw_v);
    gn_kernel<<<BB * 2, 256>>>(w1, b1, gamma, beta);

    // 2) operand prep for qkv GEMM
    conv_w_kernel<<<768, 256>>>(w_qkv);
    splitT_x_kernel<<<dim3(CC / 32, NN / 32, BB), dim3(32, 8)>>>(x);

    // 3) qkv = W_qkv @ x; epilogue writes qT (scaled), kT, V fp16 directly
    hmma_kernel<<<dim3(NN / 128, 768 / 128, BB), 256, HSMEM>>>(
        (const __half*)pwh_v, (const __half*)pxT_v, nullptr, nullptr,
        256, 256, 0, 256, (size_t)0, (size_t)NN * 256, (size_t)0, 2);

    // 4) logits = q^T k (scale folded into q) -> fp16 S
    hmma_kernel<<<dim3(NN / 128, NN / 128, BB), 256, HSMEM>>>(
        (const __half*)pqT_v, (const __half*)pkT_v, pS16_v, nullptr,
        256, 256, NN, 256, (size_t)NN * 256, (size_t)NN * 256, (size_t)NN * NN, 1);

    // 5) softmax rows -> fp16 P
    softmax_kernel<<<BB * NN, 256>>>((const __half*)pS16_v, (__half*)pP_v);

    // 6) out = V · P^T + x*xh*xw  (ELA fused into epilogue)
    hmma_kernel<<<dim3(NN / 128, CC / 128, BB), 256, HSMEM>>>(
        (const __half*)pv_v, (const __half*)pP_v, out, x,
        4096, 4096, NN, 4096, (size_t)CC * 4096, (size_t)NN * 4096, (size_t)CC * NN, 3);
}